// round 15
// baseline (speedup 1.0000x reference)
#include <cuda_runtime.h>
#include <cuda_bf16.h>
#include <math.h>
#include <stdint.h>

#define DIMM  768
#define HEADS 12
#define DHEAD 64
#define INNER 768
#define MLPD  3072
#define BB    8
#define SEQ   1024
#define ROWS  (BB*SEQ)   /* 8192 */
#define DEPTH 6
#define SCALE 0.125f     /* 64^-0.5 */
#define NQKV  (3*INNER)
#define QKVW  (NQKV/2)   /* words per row in split-bf16 qkv plane: 1152 */
#define QPLANE ((size_t)ROWS*QKVW)   /* words per hi/lo plane */

// ---------------- scratch (device globals: no allocations allowed) ----------
__device__ __align__(16) float g_qkv[(size_t)ROWS*NQKV];   // 2 bf16 planes (hi, lo)
__device__ __align__(16) float g_obuf[ROWS*INNER];
__device__ __align__(16) float g_mlp[(size_t)ROWS*MLPD];
__device__ __align__(16) __nv_bfloat16 g_ah[(size_t)ROWS*MLPD];   // LN out hi
__device__ __align__(16) __nv_bfloat16 g_al[(size_t)ROWS*MLPD];   // LN out lo
__device__ __align__(16) __nv_bfloat16 g_whq[NQKV*DIMM];
__device__ __align__(16) __nv_bfloat16 g_wlq[NQKV*DIMM];
__device__ __align__(16) __nv_bfloat16 g_who[DIMM*INNER];
__device__ __align__(16) __nv_bfloat16 g_wlo[DIMM*INNER];
__device__ __align__(16) __nv_bfloat16 g_wh1[MLPD*DIMM];
__device__ __align__(16) __nv_bfloat16 g_wl1[MLPD*DIMM];
__device__ __align__(16) __nv_bfloat16 g_wh2[DIMM*MLPD];
__device__ __align__(16) __nv_bfloat16 g_wl2[DIMM*MLPD];
__device__ float g_scal[4];

// ---------------- asm helpers ------------------------------------------------
__device__ __forceinline__ void cp_async16(void* smem, const void* gmem) {
    uint32_t s = (uint32_t)__cvta_generic_to_shared(smem);
    asm volatile("cp.async.cg.shared.global [%0], [%1], 16;\n" :: "r"(s), "l"(gmem));
}
__device__ __forceinline__ void ldsm4(uint32_t& a0, uint32_t& a1, uint32_t& a2,
                                      uint32_t& a3, const uint32_t* p) {
    uint32_t s = (uint32_t)__cvta_generic_to_shared(p);
    asm volatile("ldmatrix.sync.aligned.m8n8.x4.shared.b16 {%0,%1,%2,%3}, [%4];\n"
                 : "=r"(a0), "=r"(a1), "=r"(a2), "=r"(a3) : "r"(s));
}
__device__ __forceinline__ void ldsm2(uint32_t& a0, uint32_t& a1, const uint32_t* p) {
    uint32_t s = (uint32_t)__cvta_generic_to_shared(p);
    asm volatile("ldmatrix.sync.aligned.m8n8.x2.shared.b16 {%0,%1}, [%2];\n"
                 : "=r"(a0), "=r"(a1) : "r"(s));
}
__device__ __forceinline__ void ldsm2t(uint32_t& a0, uint32_t& a1, const uint32_t* p) {
    uint32_t s = (uint32_t)__cvta_generic_to_shared(p);
    asm volatile("ldmatrix.sync.aligned.m8n8.x2.trans.shared.b16 {%0,%1}, [%2];\n"
                 : "=r"(a0), "=r"(a1) : "r"(s));
}
__device__ __forceinline__ void mma16(float c[4], const uint32_t a[4], const uint32_t b[2]) {
    asm volatile(
        "mma.sync.aligned.m16n8k16.row.col.f32.bf16.bf16.f32 "
        "{%0,%1,%2,%3}, {%4,%5,%6,%7}, {%8,%9}, {%0,%1,%2,%3};\n"
        : "+f"(c[0]), "+f"(c[1]), "+f"(c[2]), "+f"(c[3])
        : "r"(a[0]), "r"(a[1]), "r"(a[2]), "r"(a[3]), "r"(b[0]), "r"(b[1]));
}
__device__ __forceinline__ void split2(float a, float b, uint32_t& hi, uint32_t& lo) {
    __nv_bfloat162 h = __floats2bfloat162_rn(a, b);
    hi = *reinterpret_cast<uint32_t*>(&h);
    float la = a - __bfloat162float(h.x);
    float lb = b - __bfloat162float(h.y);
    __nv_bfloat162 l = __floats2bfloat162_rn(la, lb);
    lo = *reinterpret_cast<uint32_t*>(&l);
}

// ---------------- batched abs-sum / quant / split (float4) ------------------
__global__ void abs_sum4(const float* __restrict__ w0, const float* __restrict__ w1,
                         const float* __restrict__ w2, const float* __restrict__ w3,
                         int n0, int n1, int n2, int n3, float* out) {
    int z = blockIdx.y;
    const float* w = z==0?w0 : z==1?w1 : z==2?w2 : w3;
    int n4 = (z==0?n0 : z==1?n1 : z==2?n2 : n3) >> 2;
    float s = 0.f;
    for (int i = blockIdx.x*blockDim.x + threadIdx.x; i < n4; i += gridDim.x*blockDim.x) {
        float4 v = ((const float4*)w)[i];
        s += fabsf(v.x) + fabsf(v.y) + fabsf(v.z) + fabsf(v.w);
    }
    #pragma unroll
    for (int o = 16; o; o >>= 1) s += __shfl_down_sync(0xffffffffu, s, o);
    __shared__ float sh[8];
    if ((threadIdx.x & 31) == 0) sh[threadIdx.x >> 5] = s;
    __syncthreads();
    if (threadIdx.x < 8) {
        float v = sh[threadIdx.x];
        #pragma unroll
        for (int o = 4; o; o >>= 1) v += __shfl_down_sync(0xffu, v, o);
        if (threadIdx.x == 0) atomicAdd(out + z, v);
    }
}

__global__ void quant4(const float* __restrict__ w0, const float* __restrict__ w1,
                       const float* __restrict__ w2, const float* __restrict__ w3,
                       __nv_bfloat16* __restrict__ q0, __nv_bfloat16* __restrict__ q1,
                       __nv_bfloat16* __restrict__ q2, __nv_bfloat16* __restrict__ q3,
                       const float* __restrict__ sums, int n0, int n1, int n2, int n3) {
    int z = blockIdx.y;
    const float* w = z==0?w0 : z==1?w1 : z==2?w2 : w3;
    __nv_bfloat16* q = z==0?q0 : z==1?q1 : z==2?q2 : q3;
    int n = z==0?n0 : z==1?n1 : z==2?n2 : n3;
    float s = sums[z] / (float)n + 1e-8f;
    float inv = 1.0f / s;
    int n4 = n >> 2;
    for (int i = blockIdx.x*blockDim.x + threadIdx.x; i < n4; i += gridDim.x*blockDim.x) {
        float4 v = ((const float4*)w)[i];
        float t0 = fminf(1.f, fmaxf(-1.f, rintf(v.x * inv)));   // half-to-even
        float t1 = fminf(1.f, fmaxf(-1.f, rintf(v.y * inv)));
        float t2 = fminf(1.f, fmaxf(-1.f, rintf(v.z * inv)));
        float t3 = fminf(1.f, fmaxf(-1.f, rintf(v.w * inv)));
        __nv_bfloat162 p0 = __floats2bfloat162_rn(t0, t1);
        __nv_bfloat162 p1 = __floats2bfloat162_rn(t2, t3);
        uint2 o = { *(uint32_t*)&p0, *(uint32_t*)&p1 };
        ((uint2*)q)[i] = o;
    }
}

__global__ void split4(const float* __restrict__ w0, const float* __restrict__ w1,
                       const float* __restrict__ w2, const float* __restrict__ w3,
                       __nv_bfloat16* __restrict__ h0, __nv_bfloat16* __restrict__ h1,
                       __nv_bfloat16* __restrict__ h2, __nv_bfloat16* __restrict__ h3,
                       __nv_bfloat16* __restrict__ l0, __nv_bfloat16* __restrict__ l1,
                       __nv_bfloat16* __restrict__ l2, __nv_bfloat16* __restrict__ l3,
                       int n0, int n1, int n2, int n3) {
    int z = blockIdx.y;
    const float* w = z==0?w0 : z==1?w1 : z==2?w2 : w3;
    __nv_bfloat16* hh = z==0?h0 : z==1?h1 : z==2?h2 : h3;
    __nv_bfloat16* ll = z==0?l0 : z==1?l1 : z==2?l2 : l3;
    int n4 = (z==0?n0 : z==1?n1 : z==2?n2 : n3) >> 2;
    for (int i = blockIdx.x*blockDim.x + threadIdx.x; i < n4; i += gridDim.x*blockDim.x) {
        float4 v = ((const float4*)w)[i];
        uint32_t h01, l01, h23, l23;
        split2(v.x, v.y, h01, l01);
        split2(v.z, v.w, h23, l23);
        uint2 ho = {h01, h23}, lo = {l01, l23};
        ((uint2*)hh)[i] = ho;
        ((uint2*)ll)[i] = lo;
    }
}

// ---------------- layernorm -> split bf16 (register-resident) ----------------
__device__ __forceinline__ float blockReduceSum(float v) {
    __shared__ float sh[33];
    __syncthreads();
    int lane = threadIdx.x & 31, wid = threadIdx.x >> 5;
    #pragma unroll
    for (int o = 16; o; o >>= 1) v += __shfl_down_sync(0xffffffffu, v, o);
    if (!lane) sh[wid] = v;
    __syncthreads();
    if (threadIdx.x < 8) {
        float t = sh[threadIdx.x];
        #pragma unroll
        for (int o = 4; o; o >>= 1) t += __shfl_down_sync(0xffu, t, o);
        if (!threadIdx.x) sh[32] = t;
    }
    __syncthreads();
    return sh[32];
}

__global__ void __launch_bounds__(256) ln_kernel(const float* __restrict__ x,
                                                 __nv_bfloat16* __restrict__ yh,
                                                 __nv_bfloat16* __restrict__ yl,
                                                 const float* __restrict__ g,
                                                 const float* __restrict__ b,
                                                 int width) {
    int t = threadIdx.x;
    int n4 = width >> 2;
    const float4* xr = (const float4*)(x + (size_t)blockIdx.x * width);
    float4 v[3];
    float s = 0.f;
    #pragma unroll
    for (int c = 0; c < 3; c++) {
        int i = t + c*256;
        if (i < n4) {
            v[c] = xr[i];
            s += v[c].x + v[c].y + v[c].z + v[c].w;
        }
    }
    float m = blockReduceSum(s) / (float)width;
    float v2 = 0.f;
    #pragma unroll
    for (int c = 0; c < 3; c++) {
        int i = t + c*256;
        if (i < n4) {
            float dx = v[c].x - m, dy = v[c].y - m, dz = v[c].z - m, dw = v[c].w - m;
            v2 += dx*dx + dy*dy + dz*dz + dw*dw;
        }
    }
    float var = blockReduceSum(v2) / (float)width;
    float r = rsqrtf(var + 1e-5f);
    uint2* yhr = (uint2*)(yh + (size_t)blockIdx.x * width);
    uint2* ylr = (uint2*)(yl + (size_t)blockIdx.x * width);
    #pragma unroll
    for (int c = 0; c < 3; c++) {
        int i = t + c*256;
        if (i < n4) {
            float4 gg = ((const float4*)g)[i];
            float4 bb = ((const float4*)b)[i];
            float o0 = (v[c].x - m) * r * gg.x + bb.x;
            float o1 = (v[c].y - m) * r * gg.y + bb.y;
            float o2 = (v[c].z - m) * r * gg.z + bb.z;
            float o3 = (v[c].w - m) * r * gg.w + bb.w;
            uint32_t h01, l01, h23, l23;
            split2(o0, o1, h01, l01);
            split2(o2, o3, h23, l23);
            uint2 ho = {h01, h23}, lo = {l01, l23};
            yhr[i] = ho;
            ylr[i] = lo;
        }
    }
}

// ---------------- bf16 tensor-core GEMM (2-stage, 1 sync/step) ---------------
// C = s*(A @ W^T) + bias [+gelu] [+resid]
// EPI: 0 = fp32 out, 1 = fp32 out + GELU, 2 = split-bf16 out (QKV; Q pre-scaled)
// NT: CTA tile N-width (128 default; 64 for N=768 GEMMs to fix wave quantization)
// BK: 64 for 2-chain; 32 for 3-chain (keeps 2 CTA/SM).
template<int CHAINS> struct GCfg {
    static const int BK  = (CHAINS == 2) ? 64 : 32;
    static const int WPR = BK / 2;          // words per row chunk
    static const int GW  = WPR + 4;         // padded row stride (words)
    static const int GT  = 128 * GW;        // words per array per stage
    static const int SM  = 2 * (CHAINS + 1) * GT * 4;   // smem bytes
};
#define GSMEM2 (GCfg<2>::SM)   /* 110592 */
#define GSMEM3 (GCfg<3>::SM)   /* 81920  */

template<int CHAINS, int EPI, int NT>
__global__ void __launch_bounds__(256,2) gemm_bf16(
    const uint32_t* __restrict__ AHg, const uint32_t* __restrict__ ALg,
    const uint32_t* __restrict__ WHg, const uint32_t* __restrict__ WLg,
    const float* __restrict__ sumptr, float wcount,
    const float* __restrict__ bias, const float* __restrict__ resid,
    float* __restrict__ C, int M, int N, int K)
{
    extern __shared__ uint32_t smw[];
    const int BK  = GCfg<CHAINS>::BK;
    const int WPR = GCfg<CHAINS>::WPR;
    const int GW  = GCfg<CHAINS>::GW;
    const int GT  = GCfg<CHAINS>::GT;
    const int PS  = (CHAINS + 1) * GT;
    const int NG  = BK / 16;                // k16 groups per step
    const int TPR = WPR / 4;                // copy threads per row
    const int RPP = 256 / TPR;              // rows per copy pass
    const int NTT = NT / 16;                // n8-tile pairs... n8 tiles per warp = NT/16*2
    const int NSP = NT / 2;                 // n span per warp
    int t = threadIdx.x, lane = t & 31, wid = t >> 5;
    int wm = wid & 3, wn = wid >> 2;        // 4x2 warp grid: 32m x NSP n per warp
    int bm = blockIdx.y * 128, bn = blockIdx.x * NT;
    int Kw = K >> 1;
    float acc[2][NTT][4];
    #pragma unroll
    for (int i = 0; i < 2; i++)
        #pragma unroll
        for (int j = 0; j < NTT; j++)
            #pragma unroll
            for (int u = 0; u < 4; u++) acc[i][j][u] = 0.f;

    int crow = t / TPR, cwg = (t % TPR) << 2;

    auto do_copy = [&](int slot, int kw) {
        uint32_t* S = smw + slot*PS;
        #pragma unroll
        for (int it = 0; it < 128/RPP; it++) {
            int row = it*RPP + crow;
            cp_async16(S +        row*GW + cwg, AHg + (size_t)(bm+row)*Kw + kw + cwg);
            cp_async16(S +   GT + row*GW + cwg, ALg + (size_t)(bm+row)*Kw + kw + cwg);
            if (NT == 128 || row < NT)
                cp_async16(S + 2*GT + row*GW + cwg, WHg + (size_t)(bn+row)*Kw + kw + cwg);
            if (CHAINS == 3 && (NT == 128 || row < NT))
                cp_async16(S + 3*GT + row*GW + cwg, WLg + (size_t)(bn+row)*Kw + kw + cwg);
        }
        asm volatile("cp.async.commit_group;\n");
    };

    int nsteps = K / BK;
    do_copy(0, 0);

    int lsub = lane >> 3, lrow = lane & 7;
    int lmrow = (lsub & 1) * 8 + lrow;
    int lkoff = (lsub >> 1) * 4;
    int bl8 = lane & 7;
    int btile = lsub >> 1;
    int bkh = (lsub & 1) * 4;

    for (int i = 0; i < nsteps; i++) {
        asm volatile("cp.async.wait_group 0;\n");
        __syncthreads();
        if (i + 1 < nsteps) do_copy((i + 1) & 1, (i + 1) * WPR);

        uint32_t* S = smw + (i & 1) * PS;
        const uint32_t* AHs = S;
        const uint32_t* ALs = S + GT;
        const uint32_t* WHs = S + 2*GT;
        const uint32_t* WLs = S + 3*GT;

        #pragma unroll
        for (int g = 0; g < NG; g++) {
            uint32_t bh[NTT][2], bl[NTT][2];
            #pragma unroll
            for (int p = 0; p < NTT/2; p++) {
                int brow = wn*NSP + p*16 + btile*8 + bl8;
                ldsm4(bh[2*p][0], bh[2*p][1], bh[2*p+1][0], bh[2*p+1][1],
                      WHs + brow*GW + g*8 + bkh);
                if (CHAINS == 3)
                    ldsm4(bl[2*p][0], bl[2*p][1], bl[2*p+1][0], bl[2*p+1][1],
                          WLs + brow*GW + g*8 + bkh);
            }
            uint32_t ah[2][4], al[2][4];
            #pragma unroll
            for (int ii = 0; ii < 2; ii++) {
                int mr = wm*32 + ii*16 + lmrow;
                int kc = g*8 + lkoff;
                ldsm4(ah[ii][0], ah[ii][1], ah[ii][2], ah[ii][3], AHs + mr*GW + kc);
                ldsm4(al[ii][0], al[ii][1], al[ii][2], al[ii][3], ALs + mr*GW + kc);
            }
            // hi chain first (independent accumulators), then lo chain
            #pragma unroll
            for (int ii = 0; ii < 2; ii++)
                #pragma unroll
                for (int j = 0; j < NTT; j++)
                    mma16(acc[ii][j], ah[ii], bh[j]);
            #pragma unroll
            for (int ii = 0; ii < 2; ii++)
                #pragma unroll
                for (int j = 0; j < NTT; j++)
                    mma16(acc[ii][j], al[ii], bh[j]);
            if (CHAINS == 3) {
                #pragma unroll
                for (int ii = 0; ii < 2; ii++)
                    #pragma unroll
                    for (int j = 0; j < NTT; j++)
                        mma16(acc[ii][j], ah[ii], bl[j]);
            }
        }
    }

    float s = 1.0f;
    if (sumptr) s = sumptr[0] / wcount + 1e-8f;
    #pragma unroll
    for (int i = 0; i < 2; i++) {
        int r0 = bm + wm*32 + i*16 + (lane >> 2);
        #pragma unroll
        for (int j = 0; j < NTT; j++) {
            int c0 = bn + wn*NSP + j*8 + ((lane & 3) << 1);
            float v[4] = {acc[i][j][0]*s, acc[i][j][1]*s, acc[i][j][2]*s, acc[i][j][3]*s};
            if (bias) { v[0] += bias[c0]; v[1] += bias[c0+1]; v[2] += bias[c0]; v[3] += bias[c0+1]; }
            if (EPI == 1) {
                #pragma unroll
                for (int u = 0; u < 4; u++)
                    v[u] = v[u] * 0.5f * (1.0f + erff(v[u] * 0.70710678118654752f));
            }
            if (resid) {
                float2 r1 = *(const float2*)(resid + (size_t)r0*N + c0);
                float2 r2 = *(const float2*)(resid + (size_t)(r0+8)*N + c0);
                v[0] += r1.x; v[1] += r1.y; v[2] += r2.x; v[3] += r2.y;
            }
            if (EPI == 2) {
                float mult = (c0 < INNER) ? SCALE : 1.0f;
                uint32_t* Ch = (uint32_t*)C;
                uint32_t* Cl = Ch + QPLANE;
                uint32_t h01, l01, h23, l23;
                split2(v[0]*mult, v[1]*mult, h01, l01);
                split2(v[2]*mult, v[3]*mult, h23, l23);
                int cw = c0 >> 1, Nw = N >> 1;
                Ch[(size_t)r0*Nw + cw]     = h01; Cl[(size_t)r0*Nw + cw]     = l01;
                Ch[(size_t)(r0+8)*Nw + cw] = h23; Cl[(size_t)(r0+8)*Nw + cw] = l23;
            } else {
                *(float2*)(C + (size_t)r0*N + c0)     = make_float2(v[0], v[1]);
                *(float2*)(C + (size_t)(r0+8)*N + c0) = make_float2(v[2], v[3]);
            }
        }
    }
}

// ---------------- tensor-core flash attention (pre-split bf16 input) ---------
#define AW 36    /* words per 64-dhead row (32 + 4 pad; 144B, 16B-aligned) */
#define AQW (128*AW)
#define AKW (64*AW)
#define AFSMEM ((2*AQW + 4*AKW)*4)   /* 73728 B */

__global__ void __launch_bounds__(256,2) attn_flash(const uint32_t* __restrict__ qh,
                                                    const uint32_t* __restrict__ ql,
                                                    float* __restrict__ O) {
    extern __shared__ uint32_t asw[];
    uint32_t* Qh = asw;
    uint32_t* Ql = asw + AQW;
    uint32_t* Kh = asw + 2*AQW;
    uint32_t* Kl = Kh + AKW;
    uint32_t* Vh = Kl + AKW;
    uint32_t* Vl = Vh + AKW;

    int t = threadIdx.x, lane = t & 31, wid = t >> 5;
    int bh = blockIdx.y;
    int b = bh / HEADS, hh = bh % HEADS;
    int m0 = blockIdx.x * 128;
    int hw = hh * (DHEAD/2);             // 32-word head offset

    #pragma unroll
    for (int it = 0; it < 4; it++) {
        int idx = it*256 + t;
        int row = idx >> 3, wg = (idx & 7) << 2;
        size_t src = (size_t)(b*SEQ + m0 + row) * QKVW + hw + wg;
        *(uint4*)(Qh + row*AW + wg) = *(const uint4*)(qh + src);
        *(uint4*)(Ql + row*AW + wg) = *(const uint4*)(ql + src);
    }
    __syncthreads();

    int lsub = lane >> 3, lrow = lane & 7;
    int mr = wid*16 + (lsub & 1)*8 + lrow;
    int lk = (lsub >> 1) * 4;
    uint32_t qfh[4][4], qfl[4][4];
    #pragma unroll
    for (int g = 0; g < 4; g++) {
        ldsm4(qfh[g][0], qfh[g][1], qfh[g][2], qfh[g][3], Qh + mr*AW + g*8 + lk);
        ldsm4(qfl[g][0], qfl[g][1], qfl[g][2], qfl[g][3], Ql + mr*AW + g*8 + lk);
    }

    float mi0 = -1e30f, mi1 = -1e30f, li0 = 0.f, li1 = 0.f;
    float acc[8][4] = {};

    for (int kv = 0; kv < SEQ; kv += 64) {
        __syncthreads();
        #pragma unroll
        for (int it = 0; it < 2; it++) {
            int idx = it*256 + t;
            int row = idx >> 3, wg = (idx & 7) << 2;
            size_t rb = (size_t)(b*SEQ + kv + row) * QKVW;
            int w = row*AW + wg;
            *(uint4*)(Kh + w) = *(const uint4*)(qh + rb + (INNER/2)   + hw + wg);
            *(uint4*)(Kl + w) = *(const uint4*)(ql + rb + (INNER/2)   + hw + wg);
            *(uint4*)(Vh + w) = *(const uint4*)(qh + rb + INNER       + hw + wg);
            *(uint4*)(Vl + w) = *(const uint4*)(ql + rb + INNER       + hw + wg);
        }
        __syncthreads();

        float s[8][4] = {};
        int koff = ((lane >> 3) & 1) * 4;
        #pragma unroll
        for (int g = 0; g < 4; g++) {
            #pragma unroll
            for (int j = 0; j < 8; j++) {
                const uint32_t* pk = Kh + (j*8 + (lane & 7))*AW + g*8 + koff;
                uint32_t bhv[2], blv[2];
                ldsm2(bhv[0], bhv[1], pk);
                ldsm2(blv[0], blv[1], Kl + (j*8 + (lane & 7))*AW + g*8 + koff);
                mma16(s[j], qfh[g], bhv);
                mma16(s[j], qfl[g], bhv);
                mma16(s[j], qfh[g], blv);
            }
        }

        float rm0 = -1e30f, rm1 = -1e30f;
        #pragma unroll
        for (int j = 0; j < 8; j++) {
            rm0 = fmaxf(rm0, fmaxf(s[j][0], s[j][1]));
            rm1 = fmaxf(rm1, fmaxf(s[j][2], s[j][3]));
        }
        rm0 = fmaxf(rm0, __shfl_xor_sync(0xffffffffu, rm0, 1));
        rm0 = fmaxf(rm0, __shfl_xor_sync(0xffffffffu, rm0, 2));
        rm1 = fmaxf(rm1, __shfl_xor_sync(0xffffffffu, rm1, 1));
        rm1 = fmaxf(rm1, __shfl_xor_sync(0xffffffffu, rm1, 2));
        float mn0 = fmaxf(mi0, rm0), mn1 = fmaxf(mi1, rm1);
        float f0 = __expf(mi0 - mn0), f1 = __expf(mi1 - mn1);
        mi0 = mn0; mi1 = mn1;
        float sum0 = 0.f, sum1 = 0.f;
        #pragma unroll
        for (int j = 0; j < 8; j++) {
            s[j][0] = __expf(s[j][0] - mn0); s[j][1] = __expf(s[j][1] - mn0);
            s[j][2] = __expf(s[j][2] - mn1); s[j][3] = __expf(s[j][3] - mn1);
            sum0 += s[j][0] + s[j][1];
            sum1 += s[j][2] + s[j][3];
        }
        sum0 += __shfl_xor_sync(0xffffffffu, sum0, 1);
        sum0 += __shfl_xor_sync(0xffffffffu, sum0, 2);
        sum1 += __shfl_xor_sync(0xffffffffu, sum1, 1);
        sum1 += __shfl_xor_sync(0xffffffffu, sum1, 2);
        li0 = li0*f0 + sum0; li1 = li1*f1 + sum1;
        #pragma unroll
        for (int j = 0; j < 8; j++) {
            acc[j][0] *= f0; acc[j][1] *= f0;
            acc[j][2] *= f1; acc[j][3] *= f1;
        }

        #pragma unroll
        for (int g = 0; g < 4; g++) {
            uint32_t aph[4], apl[4];
            split2(s[2*g][0],   s[2*g][1],   aph[0], apl[0]);
            split2(s[2*g][2],   s[2*g][3],   aph[1], apl[1]);
            split2(s[2*g+1][0], s[2*g+1][1], aph[2], apl[2]);
            split2(s[2*g+1][2], s[2*g+1][3], aph[3], apl[3]);
            #pragma unroll
            for (int j = 0; j < 8; j++) {
                const uint32_t* pv = Vh + (g*16 + (lane & 15))*AW + j*4;
                uint32_t bhv[2], blv[2];
                ldsm2t(bhv[0], bhv[1], pv);
                ldsm2t(blv[0], blv[1], Vl + (g*16 + (lane & 15))*AW + j*4);
                mma16(acc[j], aph, bhv);
                mma16(acc[j], apl, bhv);
                mma16(acc[j], aph, blv);
            }
        }
    }

    float inv0 = 1.0f / li0, inv1 = 1.0f / li1;
    int r = m0 + wid*16 + (lane >> 2);
    #pragma unroll
    for (int j = 0; j < 8; j++) {
        int col = hh*DHEAD + j*8 + ((lane & 3) << 1);
        float2 o0 = {acc[j][0]*inv0, acc[j][1]*inv0};
        float2 o1 = {acc[j][2]*inv1, acc[j][3]*inv1};
        *(float2*)(O + ((size_t)b*SEQ + r)*INNER + col)     = o0;
        *(float2*)(O + ((size_t)b*SEQ + r + 8)*INNER + col) = o1;
    }
}

// ---------------- host driver -----------------------------------------------
extern "C" void kernel_launch(void* const* d_in, const int* in_sizes, int n_in,
                              void* d_out, int out_size) {
    const float* x    = (const float*)d_in[0];
    const float* ln1g = (const float*)d_in[1];
    const float* ln1b = (const float*)d_in[2];
    const float* Wqkv = (const float*)d_in[3];
    const float* ln2g = (const float*)d_in[4];
    const float* ln2b = (const float*)d_in[5];
    const float* Wo   = (const float*)d_in[6];
    const float* bo   = (const float*)d_in[7];
    const float* f1g  = (const float*)d_in[8];
    const float* f1b  = (const float*)d_in[9];
    const float* W1   = (const float*)d_in[10];
    const float* b1   = (const float*)d_in[11];
    const float* f2g  = (const float*)d_in[12];
    const float* f2b  = (const float*)d_in[13];
    const float* W2   = (const float*)d_in[14];
    const float* b2   = (const float*)d_in[15];
    float* h = (float*)d_out;

    float *qkv, *ob, *mlp, *scal;
    __nv_bfloat16 *ah, *al, *whq, *wlq, *who, *wlo, *wh1, *wl1, *wh2, *wl2;
    cudaGetSymbolAddress((void**)&qkv, g_qkv);
    cudaGetSymbolAddress((void**)&ob,  g_obuf);
    cudaGetSymbolAddress((void**)&mlp, g_mlp);
    cudaGetSymbolAddress((void**)&ah,  g_ah);
    cudaGetSymbolAddress((void**)&al,  g_al);
    cudaGetSymbolAddress((void**)&whq, g_whq);
    cudaGetSymbolAddress((void**)&wlq, g_wlq);
    cudaGetSymbolAddress((void**)&who, g_who);
    cudaGetSymbolAddress((void**)&wlo, g_wlo);
    cudaGetSymbolAddress((void**)&wh1, g_wh1);
    cudaGetSymbolAddress((void**)&wl1, g_wl1);
    cudaGetSymbolAddress((void**)&wh2, g_wh2);
    cudaGetSymbolAddress((void**)&wl2, g_wl2);
    cudaGetSymbolAddress((void**)&scal, g_scal);

    cudaFuncSetAttribute(gemm_bf16<2,0,128>, cudaFuncAttributeMaxDynamicSharedMemorySize, GSMEM2);
    cudaFuncSetAttribute(gemm_bf16<2,0,64>,  cudaFuncAttributeMaxDynamicSharedMemorySize, GSMEM2);
    cudaFuncSetAttribute(gemm_bf16<2,1,128>, cudaFuncAttributeMaxDynamicSharedMemorySize, GSMEM2);
    cudaFuncSetAttribute(gemm_bf16<2,2,128>, cudaFuncAttributeMaxDynamicSharedMemorySize, GSMEM2);
    cudaFuncSetAttribute(gemm_bf16<3,0,64>,  cudaFuncAttributeMaxDynamicSharedMemorySize, GSMEM3);
    cudaFuncSetAttribute(gemm_bf16<3,1,128>, cudaFuncAttributeMaxDynamicSharedMemorySize, GSMEM3);
    cudaFuncSetAttribute(gemm_bf16<3,2,128>, cudaFuncAttributeMaxDynamicSharedMemorySize, GSMEM3);
    cudaFuncSetAttribute(attn_flash,         cudaFuncAttributeMaxDynamicSharedMemorySize, AFSMEM);

    cudaMemcpyAsync(h, x, sizeof(float)*(size_t)ROWS*DIMM, cudaMemcpyDeviceToDevice);

    const int nA = NQKV*DIMM, nO = DIMM*INNER, n1 = MLPD*DIMM, n2 = DIMM*MLPD;

    for (int l = 0; l < DEPTH; l++) {
        bool tern = (l < DEPTH - 1);
        if (tern) {
            cudaMemsetAsync(scal, 0, 4*sizeof(float));
            abs_sum4<<<dim3(160,4),256>>>(
                Wqkv + (size_t)l*nA, Wo + (size_t)l*nO, W1 + (size_t)l*n1, W2 + (size_t)l*n2,
                nA, nO, n1, n2, scal);
            quant4<<<dim3(160,4),256>>>(
                Wqkv + (size_t)l*nA, Wo + (size_t)l*nO, W1 + (size_t)l*n1, W2 + (size_t)l*n2,
                whq, who, wh1, wh2, scal, nA, nO, n1, n2);
        } else {
            split4<<<dim3(160,4),256>>>(
                Wqkv + (size_t)l*nA, Wo + (size_t)l*nO, W1 + (size_t)l*n1, W2 + (size_t)l*n2,
                whq, who, wh1, wh2, wlq, wlo, wl1, wl2, nA, nO, n1, n2);
        }

        // attention block (QKV gemm emits pre-split, Q pre-scaled bf16)
        ln_kernel<<<ROWS,256>>>(h, ah, al, ln1g + l*DIMM, ln1b + l*DIMM, DIMM);
        if (tern)
            gemm_bf16<2,2,128><<<dim3(NQKV/128, ROWS/128),256,GSMEM2>>>(
                (uint32_t*)ah, (uint32_t*)al, (uint32_t*)whq, nullptr,
                scal+0, (float)nA, nullptr, nullptr, qkv, ROWS, NQKV, DIMM);
        else
            gemm_bf16<3,2,128><<<dim3(NQKV/128, ROWS/128),256,GSMEM3>>>(
                (uint32_t*)ah, (uint32_t*)al, (uint32_t*)whq, (uint32_t*)wlq,
                nullptr, 1.0f, nullptr, nullptr, qkv, ROWS, NQKV, DIMM);
        attn_flash<<<dim3(SEQ/128, BB*HEADS),256,AFSMEM>>>(
            (uint32_t*)qkv, (uint32_t*)qkv + QPLANE, ob);
        ln_kernel<<<ROWS,256>>>(ob, ah, al, ln2g + l*INNER, ln2b + l*INNER, INNER);
        if (tern)
            gemm_bf16<2,0,64><<<dim3(DIMM/64, ROWS/128),256,GSMEM2>>>(
                (uint32_t*)ah, (uint32_t*)al, (uint32_t*)who, nullptr,
                scal+1, (float)nO, bo + l*DIMM, h, h, ROWS, DIMM, INNER);
        else
            gemm_bf16<3,0,64><<<dim3(DIMM/64, ROWS/128),256,GSMEM3>>>(
                (uint32_t*)ah, (uint32_t*)al, (uint32_t*)who, (uint32_t*)wlo,
                nullptr, 1.0f, bo + l*DIMM, h, h, ROWS, DIMM, INNER);

        // MLP block (GELU fused into FF1 epilogue)
        ln_kernel<<<ROWS,256>>>(h, ah, al, f1g + l*DIMM, f1b + l*DIMM, DIMM);
        if (tern)
            gemm_bf16<2,1,128><<<dim3(MLPD/128, ROWS/128),256,GSMEM2>>>(
                (uint32_t*)ah, (uint32_t*)al, (uint32_t*)wh1, nullptr,
                scal+2, (float)n1, b1 + l*MLPD, nullptr, mlp, ROWS, MLPD, DIMM);
        else
            gemm_bf16<3,1,128><<<dim3(MLPD/128, ROWS/128),256,GSMEM3>>>(
                (uint32_t*)ah, (uint32_t*)al, (uint32_t*)wh1, (uint32_t*)wl1,
                nullptr, 1.0f, b1 + l*MLPD, nullptr, mlp, ROWS, MLPD, DIMM);
        ln_kernel<<<ROWS,256>>>(mlp, ah, al, f2g + l*MLPD, f2b + l*MLPD, MLPD);
        if (tern)
            gemm_bf16<2,0,64><<<dim3(DIMM/64, ROWS/128),256,GSMEM2>>>(
                (uint32_t*)ah, (uint32_t*)al, (uint32_t*)wh2, nullptr,
                scal+3, (float)n2, b2 + l*DIMM, h, h, ROWS, DIMM, MLPD);
        else
            gemm_bf16<3,0,64><<<dim3(DIMM/64, ROWS/128),256,GSMEM3>>>(
                (uint32_t*)ah, (uint32_t*)al, (uint32_t*)wh2, (uint32_t*)wl2,
                nullptr, 1.0f, b2 + l*DIMM, h, h, ROWS, DIMM, MLPD);
    }
}

// round 16
// speedup vs baseline: 1.0324x; 1.0324x over previous
#include <cuda_runtime.h>
#include <cuda_bf16.h>
#include <math.h>
#include <stdint.h>

#define DIMM  768
#define HEADS 12
#define DHEAD 64
#define INNER 768
#define MLPD  3072
#define BB    8
#define SEQ   1024
#define ROWS  (BB*SEQ)   /* 8192 */
#define DEPTH 6
#define SCALE 0.125f     /* 64^-0.5 */
#define NQKV  (3*INNER)
#define QKVW  (NQKV/2)   /* words per row in split-bf16 qkv plane: 1152 */
#define QPLANE ((size_t)ROWS*QKVW)   /* words per hi/lo plane */
#define PPLANE ((size_t)ROWS*DIMM)   /* floats per split-K partial plane */

// ---------------- scratch (device globals: no allocations allowed) ----------
__device__ __align__(16) float g_qkv[(size_t)ROWS*NQKV];   // 2 bf16 planes (hi, lo)
__device__ __align__(16) float g_obuf[ROWS*INNER];
__device__ __align__(16) float g_mlp[(size_t)ROWS*MLPD];
__device__ __align__(16) float g_part[2*PPLANE];           // split-K partials
__device__ __align__(16) __nv_bfloat16 g_ah[(size_t)ROWS*MLPD];   // LN out hi
__device__ __align__(16) __nv_bfloat16 g_al[(size_t)ROWS*MLPD];   // LN out lo
__device__ __align__(16) __nv_bfloat16 g_whq[NQKV*DIMM];
__device__ __align__(16) __nv_bfloat16 g_wlq[NQKV*DIMM];
__device__ __align__(16) __nv_bfloat16 g_who[DIMM*INNER];
__device__ __align__(16) __nv_bfloat16 g_wlo[DIMM*INNER];
__device__ __align__(16) __nv_bfloat16 g_wh1[MLPD*DIMM];
__device__ __align__(16) __nv_bfloat16 g_wl1[MLPD*DIMM];
__device__ __align__(16) __nv_bfloat16 g_wh2[DIMM*MLPD];
__device__ __align__(16) __nv_bfloat16 g_wl2[DIMM*MLPD];
__device__ float g_scal[4];

// ---------------- asm helpers ------------------------------------------------
__device__ __forceinline__ void cp_async16(void* smem, const void* gmem) {
    uint32_t s = (uint32_t)__cvta_generic_to_shared(smem);
    asm volatile("cp.async.cg.shared.global [%0], [%1], 16;\n" :: "r"(s), "l"(gmem));
}
__device__ __forceinline__ void ldsm4(uint32_t& a0, uint32_t& a1, uint32_t& a2,
                                      uint32_t& a3, const uint32_t* p) {
    uint32_t s = (uint32_t)__cvta_generic_to_shared(p);
    asm volatile("ldmatrix.sync.aligned.m8n8.x4.shared.b16 {%0,%1,%2,%3}, [%4];\n"
                 : "=r"(a0), "=r"(a1), "=r"(a2), "=r"(a3) : "r"(s));
}
__device__ __forceinline__ void ldsm2(uint32_t& a0, uint32_t& a1, const uint32_t* p) {
    uint32_t s = (uint32_t)__cvta_generic_to_shared(p);
    asm volatile("ldmatrix.sync.aligned.m8n8.x2.shared.b16 {%0,%1}, [%2];\n"
                 : "=r"(a0), "=r"(a1) : "r"(s));
}
__device__ __forceinline__ void ldsm2t(uint32_t& a0, uint32_t& a1, const uint32_t* p) {
    uint32_t s = (uint32_t)__cvta_generic_to_shared(p);
    asm volatile("ldmatrix.sync.aligned.m8n8.x2.trans.shared.b16 {%0,%1}, [%2];\n"
                 : "=r"(a0), "=r"(a1) : "r"(s));
}
__device__ __forceinline__ void mma16(float c[4], const uint32_t a[4], const uint32_t b[2]) {
    asm volatile(
        "mma.sync.aligned.m16n8k16.row.col.f32.bf16.bf16.f32 "
        "{%0,%1,%2,%3}, {%4,%5,%6,%7}, {%8,%9}, {%0,%1,%2,%3};\n"
        : "+f"(c[0]), "+f"(c[1]), "+f"(c[2]), "+f"(c[3])
        : "r"(a[0]), "r"(a[1]), "r"(a[2]), "r"(a[3]), "r"(b[0]), "r"(b[1]));
}
__device__ __forceinline__ void split2(float a, float b, uint32_t& hi, uint32_t& lo) {
    __nv_bfloat162 h = __floats2bfloat162_rn(a, b);
    hi = *reinterpret_cast<uint32_t*>(&h);
    float la = a - __bfloat162float(h.x);
    float lb = b - __bfloat162float(h.y);
    __nv_bfloat162 l = __floats2bfloat162_rn(la, lb);
    lo = *reinterpret_cast<uint32_t*>(&l);
}

// ---------------- batched abs-sum / quant / split (float4) ------------------
__global__ void abs_sum4(const float* __restrict__ w0, const float* __restrict__ w1,
                         const float* __restrict__ w2, const float* __restrict__ w3,
                         int n0, int n1, int n2, int n3, float* out) {
    int z = blockIdx.y;
    const float* w = z==0?w0 : z==1?w1 : z==2?w2 : w3;
    int n4 = (z==0?n0 : z==1?n1 : z==2?n2 : n3) >> 2;
    float s = 0.f;
    for (int i = blockIdx.x*blockDim.x + threadIdx.x; i < n4; i += gridDim.x*blockDim.x) {
        float4 v = ((const float4*)w)[i];
        s += fabsf(v.x) + fabsf(v.y) + fabsf(v.z) + fabsf(v.w);
    }
    #pragma unroll
    for (int o = 16; o; o >>= 1) s += __shfl_down_sync(0xffffffffu, s, o);
    __shared__ float sh[8];
    if ((threadIdx.x & 31) == 0) sh[threadIdx.x >> 5] = s;
    __syncthreads();
    if (threadIdx.x < 8) {
        float v = sh[threadIdx.x];
        #pragma unroll
        for (int o = 4; o; o >>= 1) v += __shfl_down_sync(0xffu, v, o);
        if (threadIdx.x == 0) atomicAdd(out + z, v);
    }
}

__global__ void quant4(const float* __restrict__ w0, const float* __restrict__ w1,
                       const float* __restrict__ w2, const float* __restrict__ w3,
                       __nv_bfloat16* __restrict__ q0, __nv_bfloat16* __restrict__ q1,
                       __nv_bfloat16* __restrict__ q2, __nv_bfloat16* __restrict__ q3,
                       const float* __restrict__ sums, int n0, int n1, int n2, int n3) {
    int z = blockIdx.y;
    const float* w = z==0?w0 : z==1?w1 : z==2?w2 : w3;
    __nv_bfloat16* q = z==0?q0 : z==1?q1 : z==2?q2 : q3;
    int n = z==0?n0 : z==1?n1 : z==2?n2 : n3;
    float s = sums[z] / (float)n + 1e-8f;
    float inv = 1.0f / s;
    int n4 = n >> 2;
    for (int i = blockIdx.x*blockDim.x + threadIdx.x; i < n4; i += gridDim.x*blockDim.x) {
        float4 v = ((const float4*)w)[i];
        float t0 = fminf(1.f, fmaxf(-1.f, rintf(v.x * inv)));   // half-to-even
        float t1 = fminf(1.f, fmaxf(-1.f, rintf(v.y * inv)));
        float t2 = fminf(1.f, fmaxf(-1.f, rintf(v.z * inv)));
        float t3 = fminf(1.f, fmaxf(-1.f, rintf(v.w * inv)));
        __nv_bfloat162 p0 = __floats2bfloat162_rn(t0, t1);
        __nv_bfloat162 p1 = __floats2bfloat162_rn(t2, t3);
        uint2 o = { *(uint32_t*)&p0, *(uint32_t*)&p1 };
        ((uint2*)q)[i] = o;
    }
}

__global__ void split4(const float* __restrict__ w0, const float* __restrict__ w1,
                       const float* __restrict__ w2, const float* __restrict__ w3,
                       __nv_bfloat16* __restrict__ h0, __nv_bfloat16* __restrict__ h1,
                       __nv_bfloat16* __restrict__ h2, __nv_bfloat16* __restrict__ h3,
                       __nv_bfloat16* __restrict__ l0, __nv_bfloat16* __restrict__ l1,
                       __nv_bfloat16* __restrict__ l2, __nv_bfloat16* __restrict__ l3,
                       int n0, int n1, int n2, int n3) {
    int z = blockIdx.y;
    const float* w = z==0?w0 : z==1?w1 : z==2?w2 : w3;
    __nv_bfloat16* hh = z==0?h0 : z==1?h1 : z==2?h2 : h3;
    __nv_bfloat16* ll = z==0?l0 : z==1?l1 : z==2?l2 : l3;
    int n4 = (z==0?n0 : z==1?n1 : z==2?n2 : n3) >> 2;
    for (int i = blockIdx.x*blockDim.x + threadIdx.x; i < n4; i += gridDim.x*blockDim.x) {
        float4 v = ((const float4*)w)[i];
        uint32_t h01, l01, h23, l23;
        split2(v.x, v.y, h01, l01);
        split2(v.z, v.w, h23, l23);
        uint2 ho = {h01, h23}, lo = {l01, l23};
        ((uint2*)hh)[i] = ho;
        ((uint2*)ll)[i] = lo;
    }
}

// ---------------- split-K reduction: C = (p0+p1)*s + bias + resid -----------
__global__ void __launch_bounds__(256) reduce_add(
    const float4* __restrict__ p0, const float4* __restrict__ p1,
    const float* __restrict__ sumptr, float wcount,
    const float4* __restrict__ bias, const float4* __restrict__ resid,
    float4* __restrict__ C, int n4, int N4)
{
    float s = 1.0f;
    if (sumptr) s = sumptr[0] / wcount + 1e-8f;
    int i = blockIdx.x * blockDim.x + threadIdx.x;
    if (i < n4) {
        float4 a = p0[i], b = p1[i];
        float4 bb = bias[i % N4];
        float4 r = resid[i];
        C[i] = make_float4((a.x + b.x) * s + bb.x + r.x,
                           (a.y + b.y) * s + bb.y + r.y,
                           (a.z + b.z) * s + bb.z + r.z,
                           (a.w + b.w) * s + bb.w + r.w);
    }
}

// ---------------- layernorm -> split bf16 (register-resident) ----------------
__device__ __forceinline__ float blockReduceSum(float v) {
    __shared__ float sh[33];
    __syncthreads();
    int lane = threadIdx.x & 31, wid = threadIdx.x >> 5;
    #pragma unroll
    for (int o = 16; o; o >>= 1) v += __shfl_down_sync(0xffffffffu, v, o);
    if (!lane) sh[wid] = v;
    __syncthreads();
    if (threadIdx.x < 8) {
        float t = sh[threadIdx.x];
        #pragma unroll
        for (int o = 4; o; o >>= 1) t += __shfl_down_sync(0xffu, t, o);
        if (!threadIdx.x) sh[32] = t;
    }
    __syncthreads();
    return sh[32];
}

__global__ void __launch_bounds__(256) ln_kernel(const float* __restrict__ x,
                                                 __nv_bfloat16* __restrict__ yh,
                                                 __nv_bfloat16* __restrict__ yl,
                                                 const float* __restrict__ g,
                                                 const float* __restrict__ b,
                                                 int width) {
    int t = threadIdx.x;
    int n4 = width >> 2;
    const float4* xr = (const float4*)(x + (size_t)blockIdx.x * width);
    float4 v[3];
    float s = 0.f;
    #pragma unroll
    for (int c = 0; c < 3; c++) {
        int i = t + c*256;
        if (i < n4) {
            v[c] = xr[i];
            s += v[c].x + v[c].y + v[c].z + v[c].w;
        }
    }
    float m = blockReduceSum(s) / (float)width;
    float v2 = 0.f;
    #pragma unroll
    for (int c = 0; c < 3; c++) {
        int i = t + c*256;
        if (i < n4) {
            float dx = v[c].x - m, dy = v[c].y - m, dz = v[c].z - m, dw = v[c].w - m;
            v2 += dx*dx + dy*dy + dz*dz + dw*dw;
        }
    }
    float var = blockReduceSum(v2) / (float)width;
    float r = rsqrtf(var + 1e-5f);
    uint2* yhr = (uint2*)(yh + (size_t)blockIdx.x * width);
    uint2* ylr = (uint2*)(yl + (size_t)blockIdx.x * width);
    #pragma unroll
    for (int c = 0; c < 3; c++) {
        int i = t + c*256;
        if (i < n4) {
            float4 gg = ((const float4*)g)[i];
            float4 bb = ((const float4*)b)[i];
            float o0 = (v[c].x - m) * r * gg.x + bb.x;
            float o1 = (v[c].y - m) * r * gg.y + bb.y;
            float o2 = (v[c].z - m) * r * gg.z + bb.z;
            float o3 = (v[c].w - m) * r * gg.w + bb.w;
            uint32_t h01, l01, h23, l23;
            split2(o0, o1, h01, l01);
            split2(o2, o3, h23, l23);
            uint2 ho = {h01, h23}, lo = {l01, l23};
            yhr[i] = ho;
            ylr[i] = lo;
        }
    }
}

// ---------------- bf16 tensor-core GEMM (2-stage, 1 sync/step) ---------------
// C = s*(A @ W^T) + bias [+gelu] [+resid]
// EPI: 0 fp32 out, 1 fp32+GELU, 2 split-bf16 out (QKV), 3 raw partial (split-K)
// SPLIT: K-range split across blockIdx.z (partials reduced by reduce_add)
template<int CHAINS> struct GCfg {
    static const int BK  = (CHAINS == 2) ? 64 : 32;
    static const int WPR = BK / 2;          // words per row chunk
    static const int GW  = WPR + 4;         // padded row stride (words)
    static const int GT  = 128 * GW;        // words per array per stage
    static const int SM  = 2 * (CHAINS + 1) * GT * 4;   // smem bytes
};
#define GSMEM2 (GCfg<2>::SM)   /* 110592 */
#define GSMEM3 (GCfg<3>::SM)   /* 81920  */

template<int CHAINS, int EPI, int SPLIT>
__global__ void __launch_bounds__(256,2) gemm_bf16(
    const uint32_t* __restrict__ AHg, const uint32_t* __restrict__ ALg,
    const uint32_t* __restrict__ WHg, const uint32_t* __restrict__ WLg,
    const float* __restrict__ sumptr, float wcount,
    const float* __restrict__ bias, const float* __restrict__ resid,
    float* __restrict__ C, int M, int N, int K)
{
    extern __shared__ uint32_t smw[];
    const int BK  = GCfg<CHAINS>::BK;
    const int WPR = GCfg<CHAINS>::WPR;
    const int GW  = GCfg<CHAINS>::GW;
    const int GT  = GCfg<CHAINS>::GT;
    const int PS  = (CHAINS + 1) * GT;
    const int NG  = BK / 16;                // k16 groups per step
    const int TPR = WPR / 4;                // copy threads per row
    const int RPP = 256 / TPR;              // rows per copy pass
    int t = threadIdx.x, lane = t & 31, wid = t >> 5;
    int wm = wid & 3, wn = wid >> 2;        // 4x2 warp grid: 32m x 64n per warp
    int bm = blockIdx.y * 128, bn = blockIdx.x * 128;
    int Kw = K >> 1;
    int kwb = (SPLIT == 2) ? (int)blockIdx.z * (Kw >> 1) : 0;
    float* Cp = (EPI == 3) ? (C + (size_t)blockIdx.z * PPLANE) : C;
    float acc[2][8][4] = {};

    int crow = t / TPR, cwg = (t % TPR) << 2;

    auto do_copy = [&](int slot, int kw) {
        uint32_t* S = smw + slot*PS;
        #pragma unroll
        for (int it = 0; it < 128/RPP; it++) {
            int row = it*RPP + crow;
            cp_async16(S +        row*GW + cwg, AHg + (size_t)(bm+row)*Kw + kw + cwg);
            cp_async16(S +   GT + row*GW + cwg, ALg + (size_t)(bm+row)*Kw + kw + cwg);
            cp_async16(S + 2*GT + row*GW + cwg, WHg + (size_t)(bn+row)*Kw + kw + cwg);
            if (CHAINS == 3)
                cp_async16(S + 3*GT + row*GW + cwg, WLg + (size_t)(bn+row)*Kw + kw + cwg);
        }
        asm volatile("cp.async.commit_group;\n");
    };

    int nsteps = K / (BK * SPLIT);
    do_copy(0, kwb);

    int lsub = lane >> 3, lrow = lane & 7;
    int lmrow = (lsub & 1) * 8 + lrow;
    int lkoff = (lsub >> 1) * 4;
    int bl8 = lane & 7;
    int btile = lsub >> 1;
    int bkh = (lsub & 1) * 4;

    for (int i = 0; i < nsteps; i++) {
        asm volatile("cp.async.wait_group 0;\n");
        __syncthreads();
        if (i + 1 < nsteps) do_copy((i + 1) & 1, kwb + (i + 1) * WPR);

        uint32_t* S = smw + (i & 1) * PS;
        const uint32_t* AHs = S;
        const uint32_t* ALs = S + GT;
        const uint32_t* WHs = S + 2*GT;
        const uint32_t* WLs = S + 3*GT;

        #pragma unroll
        for (int g = 0; g < NG; g++) {
            uint32_t bh[8][2], bl[8][2];
            #pragma unroll
            for (int p = 0; p < 4; p++) {
                int brow = wn*64 + p*16 + btile*8 + bl8;
                ldsm4(bh[2*p][0], bh[2*p][1], bh[2*p+1][0], bh[2*p+1][1],
                      WHs + brow*GW + g*8 + bkh);
                if (CHAINS == 3)
                    ldsm4(bl[2*p][0], bl[2*p][1], bl[2*p+1][0], bl[2*p+1][1],
                          WLs + brow*GW + g*8 + bkh);
            }
            uint32_t ah[2][4], al[2][4];
            #pragma unroll
            for (int ii = 0; ii < 2; ii++) {
                int mr = wm*32 + ii*16 + lmrow;
                int kc = g*8 + lkoff;
                ldsm4(ah[ii][0], ah[ii][1], ah[ii][2], ah[ii][3], AHs + mr*GW + kc);
                ldsm4(al[ii][0], al[ii][1], al[ii][2], al[ii][3], ALs + mr*GW + kc);
            }
            // hi chain first (16 independent accumulators), then lo chain
            #pragma unroll
            for (int ii = 0; ii < 2; ii++)
                #pragma unroll
                for (int j = 0; j < 8; j++)
                    mma16(acc[ii][j], ah[ii], bh[j]);
            #pragma unroll
            for (int ii = 0; ii < 2; ii++)
                #pragma unroll
                for (int j = 0; j < 8; j++)
                    mma16(acc[ii][j], al[ii], bh[j]);
            if (CHAINS == 3) {
                #pragma unroll
                for (int ii = 0; ii < 2; ii++)
                    #pragma unroll
                    for (int j = 0; j < 8; j++)
                        mma16(acc[ii][j], ah[ii], bl[j]);
            }
        }
    }

    float s = 1.0f;
    if (EPI != 3 && sumptr) s = sumptr[0] / wcount + 1e-8f;
    #pragma unroll
    for (int i = 0; i < 2; i++) {
        int r0 = bm + wm*32 + i*16 + (lane >> 2);
        #pragma unroll
        for (int j = 0; j < 8; j++) {
            int c0 = bn + wn*64 + j*8 + ((lane & 3) << 1);
            float v[4] = {acc[i][j][0]*s, acc[i][j][1]*s, acc[i][j][2]*s, acc[i][j][3]*s};
            if (EPI == 3) {
                *(float2*)(Cp + (size_t)r0*N + c0)     = make_float2(v[0], v[1]);
                *(float2*)(Cp + (size_t)(r0+8)*N + c0) = make_float2(v[2], v[3]);
                continue;
            }
            if (bias) { v[0] += bias[c0]; v[1] += bias[c0+1]; v[2] += bias[c0]; v[3] += bias[c0+1]; }
            if (EPI == 1) {
                #pragma unroll
                for (int u = 0; u < 4; u++)
                    v[u] = v[u] * 0.5f * (1.0f + erff(v[u] * 0.70710678118654752f));
            }
            if (resid) {
                float2 r1 = *(const float2*)(resid + (size_t)r0*N + c0);
                float2 r2 = *(const float2*)(resid + (size_t)(r0+8)*N + c0);
                v[0] += r1.x; v[1] += r1.y; v[2] += r2.x; v[3] += r2.y;
            }
            if (EPI == 2) {
                float mult = (c0 < INNER) ? SCALE : 1.0f;
                uint32_t* Ch = (uint32_t*)C;
                uint32_t* Cl = Ch + QPLANE;
                uint32_t h01, l01, h23, l23;
                split2(v[0]*mult, v[1]*mult, h01, l01);
                split2(v[2]*mult, v[3]*mult, h23, l23);
                int cw = c0 >> 1, Nw = N >> 1;
                Ch[(size_t)r0*Nw + cw]     = h01; Cl[(size_t)r0*Nw + cw]     = l01;
                Ch[(size_t)(r0+8)*Nw + cw] = h23; Cl[(size_t)(r0+8)*Nw + cw] = l23;
            } else {
                *(float2*)(C + (size_t)r0*N + c0)     = make_float2(v[0], v[1]);
                *(float2*)(C + (size_t)(r0+8)*N + c0) = make_float2(v[2], v[3]);
            }
        }
    }
}

// ---------------- tensor-core flash attention (pre-split bf16 input) ---------
#define AW 36    /* words per 64-dhead row (32 + 4 pad; 144B, 16B-aligned) */
#define AQW (128*AW)
#define AKW (64*AW)
#define AFSMEM ((2*AQW + 4*AKW)*4)   /* 73728 B */

__global__ void __launch_bounds__(256,2) attn_flash(const uint32_t* __restrict__ qh,
                                                    const uint32_t* __restrict__ ql,
                                                    float* __restrict__ O) {
    extern __shared__ uint32_t asw[];
    uint32_t* Qh = asw;
    uint32_t* Ql = asw + AQW;
    uint32_t* Kh = asw + 2*AQW;
    uint32_t* Kl = Kh + AKW;
    uint32_t* Vh = Kl + AKW;
    uint32_t* Vl = Vh + AKW;

    int t = threadIdx.x, lane = t & 31, wid = t >> 5;
    int bh = blockIdx.y;
    int b = bh / HEADS, hh = bh % HEADS;
    int m0 = blockIdx.x * 128;
    int hw = hh * (DHEAD/2);             // 32-word head offset

    #pragma unroll
    for (int it = 0; it < 4; it++) {
        int idx = it*256 + t;
        int row = idx >> 3, wg = (idx & 7) << 2;
        size_t src = (size_t)(b*SEQ + m0 + row) * QKVW + hw + wg;
        *(uint4*)(Qh + row*AW + wg) = *(const uint4*)(qh + src);
        *(uint4*)(Ql + row*AW + wg) = *(const uint4*)(ql + src);
    }
    __syncthreads();

    int lsub = lane >> 3, lrow = lane & 7;
    int mr = wid*16 + (lsub & 1)*8 + lrow;
    int lk = (lsub >> 1) * 4;
    uint32_t qfh[4][4], qfl[4][4];
    #pragma unroll
    for (int g = 0; g < 4; g++) {
        ldsm4(qfh[g][0], qfh[g][1], qfh[g][2], qfh[g][3], Qh + mr*AW + g*8 + lk);
        ldsm4(qfl[g][0], qfl[g][1], qfl[g][2], qfl[g][3], Ql + mr*AW + g*8 + lk);
    }

    float mi0 = -1e30f, mi1 = -1e30f, li0 = 0.f, li1 = 0.f;
    float acc[8][4] = {};

    for (int kv = 0; kv < SEQ; kv += 64) {
        __syncthreads();
        #pragma unroll
        for (int it = 0; it < 2; it++) {
            int idx = it*256 + t;
            int row = idx >> 3, wg = (idx & 7) << 2;
            size_t rb = (size_t)(b*SEQ + kv + row) * QKVW;
            int w = row*AW + wg;
            *(uint4*)(Kh + w) = *(const uint4*)(qh + rb + (INNER/2)   + hw + wg);
            *(uint4*)(Kl + w) = *(const uint4*)(ql + rb + (INNER/2)   + hw + wg);
            *(uint4*)(Vh + w) = *(const uint4*)(qh + rb + INNER       + hw + wg);
            *(uint4*)(Vl + w) = *(const uint4*)(ql + rb + INNER       + hw + wg);
        }
        __syncthreads();

        float s[8][4] = {};
        int koff = ((lane >> 3) & 1) * 4;
        #pragma unroll
        for (int g = 0; g < 4; g++) {
            #pragma unroll
            for (int j = 0; j < 8; j++) {
                const uint32_t* pk = Kh + (j*8 + (lane & 7))*AW + g*8 + koff;
                uint32_t bhv[2], blv[2];
                ldsm2(bhv[0], bhv[1], pk);
                ldsm2(blv[0], blv[1], Kl + (j*8 + (lane & 7))*AW + g*8 + koff);
                mma16(s[j], qfh[g], bhv);
                mma16(s[j], qfl[g], bhv);
                mma16(s[j], qfh[g], blv);
            }
        }

        float rm0 = -1e30f, rm1 = -1e30f;
        #pragma unroll
        for (int j = 0; j < 8; j++) {
            rm0 = fmaxf(rm0, fmaxf(s[j][0], s[j][1]));
            rm1 = fmaxf(rm1, fmaxf(s[j][2], s[j][3]));
        }
        rm0 = fmaxf(rm0, __shfl_xor_sync(0xffffffffu, rm0, 1));
        rm0 = fmaxf(rm0, __shfl_xor_sync(0xffffffffu, rm0, 2));
        rm1 = fmaxf(rm1, __shfl_xor_sync(0xffffffffu, rm1, 1));
        rm1 = fmaxf(rm1, __shfl_xor_sync(0xffffffffu, rm1, 2));
        float mn0 = fmaxf(mi0, rm0), mn1 = fmaxf(mi1, rm1);
        float f0 = __expf(mi0 - mn0), f1 = __expf(mi1 - mn1);
        mi0 = mn0; mi1 = mn1;
        float sum0 = 0.f, sum1 = 0.f;
        #pragma unroll
        for (int j = 0; j < 8; j++) {
            s[j][0] = __expf(s[j][0] - mn0); s[j][1] = __expf(s[j][1] - mn0);
            s[j][2] = __expf(s[j][2] - mn1); s[j][3] = __expf(s[j][3] - mn1);
            sum0 += s[j][0] + s[j][1];
            sum1 += s[j][2] + s[j][3];
        }
        sum0 += __shfl_xor_sync(0xffffffffu, sum0, 1);
        sum0 += __shfl_xor_sync(0xffffffffu, sum0, 2);
        sum1 += __shfl_xor_sync(0xffffffffu, sum1, 1);
        sum1 += __shfl_xor_sync(0xffffffffu, sum1, 2);
        li0 = li0*f0 + sum0; li1 = li1*f1 + sum1;
        #pragma unroll
        for (int j = 0; j < 8; j++) {
            acc[j][0] *= f0; acc[j][1] *= f0;
            acc[j][2] *= f1; acc[j][3] *= f1;
        }

        #pragma unroll
        for (int g = 0; g < 4; g++) {
            uint32_t aph[4], apl[4];
            split2(s[2*g][0],   s[2*g][1],   aph[0], apl[0]);
            split2(s[2*g][2],   s[2*g][3],   aph[1], apl[1]);
            split2(s[2*g+1][0], s[2*g+1][1], aph[2], apl[2]);
            split2(s[2*g+1][2], s[2*g+1][3], aph[3], apl[3]);
            #pragma unroll
            for (int j = 0; j < 8; j++) {
                const uint32_t* pv = Vh + (g*16 + (lane & 15))*AW + j*4;
                uint32_t bhv[2], blv[2];
                ldsm2t(bhv[0], bhv[1], pv);
                ldsm2t(blv[0], blv[1], Vl + (g*16 + (lane & 15))*AW + j*4);
                mma16(acc[j], aph, bhv);
                mma16(acc[j], apl, bhv);
                mma16(acc[j], aph, blv);
            }
        }
    }

    float inv0 = 1.0f / li0, inv1 = 1.0f / li1;
    int r = m0 + wid*16 + (lane >> 2);
    #pragma unroll
    for (int j = 0; j < 8; j++) {
        int col = hh*DHEAD + j*8 + ((lane & 3) << 1);
        float2 o0 = {acc[j][0]*inv0, acc[j][1]*inv0};
        float2 o1 = {acc[j][2]*inv1, acc[j][3]*inv1};
        *(float2*)(O + ((size_t)b*SEQ + r)*INNER + col)     = o0;
        *(float2*)(O + ((size_t)b*SEQ + r + 8)*INNER + col) = o1;
    }
}

// ---------------- host driver -----------------------------------------------
extern "C" void kernel_launch(void* const* d_in, const int* in_sizes, int n_in,
                              void* d_out, int out_size) {
    const float* x    = (const float*)d_in[0];
    const float* ln1g = (const float*)d_in[1];
    const float* ln1b = (const float*)d_in[2];
    const float* Wqkv = (const float*)d_in[3];
    const float* ln2g = (const float*)d_in[4];
    const float* ln2b = (const float*)d_in[5];
    const float* Wo   = (const float*)d_in[6];
    const float* bo   = (const float*)d_in[7];
    const float* f1g  = (const float*)d_in[8];
    const float* f1b  = (const float*)d_in[9];
    const float* W1   = (const float*)d_in[10];
    const float* b1   = (const float*)d_in[11];
    const float* f2g  = (const float*)d_in[12];
    const float* f2b  = (const float*)d_in[13];
    const float* W2   = (const float*)d_in[14];
    const float* b2   = (const float*)d_in[15];
    float* h = (float*)d_out;

    float *qkv, *ob, *mlp, *part, *scal;
    __nv_bfloat16 *ah, *al, *whq, *wlq, *who, *wlo, *wh1, *wl1, *wh2, *wl2;
    cudaGetSymbolAddress((void**)&qkv, g_qkv);
    cudaGetSymbolAddress((void**)&ob,  g_obuf);
    cudaGetSymbolAddress((void**)&mlp, g_mlp);
    cudaGetSymbolAddress((void**)&part, g_part);
    cudaGetSymbolAddress((void**)&ah,  g_ah);
    cudaGetSymbolAddress((void**)&al,  g_al);
    cudaGetSymbolAddress((void**)&whq, g_whq);
    cudaGetSymbolAddress((void**)&wlq, g_wlq);
    cudaGetSymbolAddress((void**)&who, g_who);
    cudaGetSymbolAddress((void**)&wlo, g_wlo);
    cudaGetSymbolAddress((void**)&wh1, g_wh1);
    cudaGetSymbolAddress((void**)&wl1, g_wl1);
    cudaGetSymbolAddress((void**)&wh2, g_wh2);
    cudaGetSymbolAddress((void**)&wl2, g_wl2);
    cudaGetSymbolAddress((void**)&scal, g_scal);

    cudaFuncSetAttribute(gemm_bf16<2,0,1>, cudaFuncAttributeMaxDynamicSharedMemorySize, GSMEM2);
    cudaFuncSetAttribute(gemm_bf16<2,1,1>, cudaFuncAttributeMaxDynamicSharedMemorySize, GSMEM2);
    cudaFuncSetAttribute(gemm_bf16<2,2,1>, cudaFuncAttributeMaxDynamicSharedMemorySize, GSMEM2);
    cudaFuncSetAttribute(gemm_bf16<2,3,2>, cudaFuncAttributeMaxDynamicSharedMemorySize, GSMEM2);
    cudaFuncSetAttribute(gemm_bf16<3,0,1>, cudaFuncAttributeMaxDynamicSharedMemorySize, GSMEM3);
    cudaFuncSetAttribute(gemm_bf16<3,1,1>, cudaFuncAttributeMaxDynamicSharedMemorySize, GSMEM3);
    cudaFuncSetAttribute(gemm_bf16<3,2,1>, cudaFuncAttributeMaxDynamicSharedMemorySize, GSMEM3);
    cudaFuncSetAttribute(gemm_bf16<3,3,2>, cudaFuncAttributeMaxDynamicSharedMemorySize, GSMEM3);
    cudaFuncSetAttribute(attn_flash,       cudaFuncAttributeMaxDynamicSharedMemorySize, AFSMEM);

    cudaMemcpyAsync(h, x, sizeof(float)*(size_t)ROWS*DIMM, cudaMemcpyDeviceToDevice);

    const int nA = NQKV*DIMM, nO = DIMM*INNER, n1 = MLPD*DIMM, n2 = DIMM*MLPD;
    const int RN4 = ROWS*DIMM/4;   // float4 count for reduce
    const int N4  = DIMM/4;

    for (int l = 0; l < DEPTH; l++) {
        bool tern = (l < DEPTH - 1);
        if (tern) {
            cudaMemsetAsync(scal, 0, 4*sizeof(float));
            abs_sum4<<<dim3(160,4),256>>>(
                Wqkv + (size_t)l*nA, Wo + (size_t)l*nO, W1 + (size_t)l*n1, W2 + (size_t)l*n2,
                nA, nO, n1, n2, scal);
            quant4<<<dim3(160,4),256>>>(
                Wqkv + (size_t)l*nA, Wo + (size_t)l*nO, W1 + (size_t)l*n1, W2 + (size_t)l*n2,
                whq, who, wh1, wh2, scal, nA, nO, n1, n2);
        } else {
            split4<<<dim3(160,4),256>>>(
                Wqkv + (size_t)l*nA, Wo + (size_t)l*nO, W1 + (size_t)l*n1, W2 + (size_t)l*n2,
                whq, who, wh1, wh2, wlq, wlo, wl1, wl2, nA, nO, n1, n2);
        }

        // attention block (QKV gemm emits pre-split, Q pre-scaled bf16)
        ln_kernel<<<ROWS,256>>>(h, ah, al, ln1g + l*DIMM, ln1b + l*DIMM, DIMM);
        if (tern)
            gemm_bf16<2,2,1><<<dim3(NQKV/128, ROWS/128),256,GSMEM2>>>(
                (uint32_t*)ah, (uint32_t*)al, (uint32_t*)whq, nullptr,
                scal+0, (float)nA, nullptr, nullptr, qkv, ROWS, NQKV, DIMM);
        else
            gemm_bf16<3,2,1><<<dim3(NQKV/128, ROWS/128),256,GSMEM3>>>(
                (uint32_t*)ah, (uint32_t*)al, (uint32_t*)whq, (uint32_t*)wlq,
                nullptr, 1.0f, nullptr, nullptr, qkv, ROWS, NQKV, DIMM);
        attn_flash<<<dim3(SEQ/128, BB*HEADS),256,AFSMEM>>>(
            (uint32_t*)qkv, (uint32_t*)qkv + QPLANE, ob);
        ln_kernel<<<ROWS,256>>>(ob, ah, al, ln2g + l*INNER, ln2b + l*INNER, INNER);
        if (tern)
            gemm_bf16<2,0,1><<<dim3(DIMM/128, ROWS/128),256,GSMEM2>>>(
                (uint32_t*)ah, (uint32_t*)al, (uint32_t*)who, nullptr,
                scal+1, (float)nO, bo + l*DIMM, h, h, ROWS, DIMM, INNER);
        else
            gemm_bf16<3,0,1><<<dim3(DIMM/128, ROWS/128),256,GSMEM3>>>(
                (uint32_t*)ah, (uint32_t*)al, (uint32_t*)who, (uint32_t*)wlo,
                nullptr, 1.0f, bo + l*DIMM, h, h, ROWS, DIMM, INNER);

        // MLP block (GELU fused into FF1 epilogue; FF2 split-K=2)
        ln_kernel<<<ROWS,256>>>(h, ah, al, f1g + l*DIMM, f1b + l*DIMM, DIMM);
        if (tern)
            gemm_bf16<2,1,1><<<dim3(MLPD/128, ROWS/128),256,GSMEM2>>>(
                (uint32_t*)ah, (uint32_t*)al, (uint32_t*)wh1, nullptr,
                scal+2, (float)n1, b1 + l*MLPD, nullptr, mlp, ROWS, MLPD, DIMM);
        else
            gemm_bf16<3,1,1><<<dim3(MLPD/128, ROWS/128),256,GSMEM3>>>(
                (uint32_t*)ah, (uint32_t*)al, (uint32_t*)wh1, (uint32_t*)wl1,
                nullptr, 1.0f, b1 + l*MLPD, nullptr, mlp, ROWS, MLPD, DIMM);
        ln_kernel<<<ROWS,256>>>(mlp, ah, al, f2g + l*MLPD, f2b + l*MLPD, MLPD);
        if (tern) {
            gemm_bf16<2,3,2><<<dim3(DIMM/128, ROWS/128, 2),256,GSMEM2>>>(
                (uint32_t*)ah, (uint32_t*)al, (uint32_t*)wh2, nullptr,
                nullptr, 1.0f, nullptr, nullptr, part, ROWS, DIMM, MLPD);
            reduce_add<<<(RN4+255)/256,256>>>(
                (const float4*)part, (const float4*)(part + PPLANE),
                scal+3, (float)n2, (const float4*)(b2 + l*DIMM),
                (const float4*)h, (float4*)h, RN4, N4);
        } else {
            gemm_bf16<3,3,2><<<dim3(DIMM/128, ROWS/128, 2),256,GSMEM3>>>(
                (uint32_t*)ah, (uint32_t*)al, (uint32_t*)wh2, (uint32_t*)wl2,
                nullptr, 1.0f, nullptr, nullptr, part, ROWS, DIMM, MLPD);
            reduce_add<<<(RN4+255)/256,256>>>(
                (const float4*)part, (const float4*)(part + PPLANE),
                nullptr, 1.0f, (const float4*)(b2 + l*DIMM),
                (const float4*)h, (float4*)h, RN4, N4);
        }
    }
}

// round 17
// speedup vs baseline: 1.0360x; 1.0035x over previous
#include <cuda_runtime.h>
#include <cuda_bf16.h>
#include <math.h>
#include <stdint.h>

#define DIMM  768
#define HEADS 12
#define DHEAD 64
#define INNER 768
#define MLPD  3072
#define BB    8
#define SEQ   1024
#define ROWS  (BB*SEQ)   /* 8192 */
#define DEPTH 6
#define SCALE 0.125f     /* 64^-0.5 */
#define NQKV  (3*INNER)
#define QKVW  (NQKV/2)   /* words per row in split-bf16 qkv plane: 1152 */
#define QPLANE ((size_t)ROWS*QKVW)   /* words per hi/lo plane */
#define PPLANE ((size_t)ROWS*DIMM)   /* floats per split-K partial plane */

// ---------------- scratch (device globals: no allocations allowed) ----------
__device__ __align__(16) float g_qkv[(size_t)ROWS*NQKV];   // 2 bf16 planes (hi, lo)
__device__ __align__(16) float g_obuf[ROWS*INNER];
__device__ __align__(16) float g_mlp[(size_t)ROWS*MLPD];
__device__ __align__(16) float g_part[2*PPLANE];           // split-K partials
__device__ __align__(16) __nv_bfloat16 g_ah[(size_t)ROWS*MLPD];   // LN out hi
__device__ __align__(16) __nv_bfloat16 g_al[(size_t)ROWS*MLPD];   // LN out lo
__device__ __align__(16) __nv_bfloat16 g_whq[NQKV*DIMM];
__device__ __align__(16) __nv_bfloat16 g_wlq[NQKV*DIMM];
__device__ __align__(16) __nv_bfloat16 g_who[DIMM*INNER];
__device__ __align__(16) __nv_bfloat16 g_wlo[DIMM*INNER];
__device__ __align__(16) __nv_bfloat16 g_wh1[MLPD*DIMM];
__device__ __align__(16) __nv_bfloat16 g_wl1[MLPD*DIMM];
__device__ __align__(16) __nv_bfloat16 g_wh2[DIMM*MLPD];
__device__ __align__(16) __nv_bfloat16 g_wl2[DIMM*MLPD];
__device__ float g_scal[4];

// ---------------- asm helpers ------------------------------------------------
__device__ __forceinline__ void cp_async16(void* smem, const void* gmem) {
    uint32_t s = (uint32_t)__cvta_generic_to_shared(smem);
    asm volatile("cp.async.cg.shared.global [%0], [%1], 16;\n" :: "r"(s), "l"(gmem));
}
__device__ __forceinline__ void ldsm4(uint32_t& a0, uint32_t& a1, uint32_t& a2,
                                      uint32_t& a3, const uint32_t* p) {
    uint32_t s = (uint32_t)__cvta_generic_to_shared(p);
    asm volatile("ldmatrix.sync.aligned.m8n8.x4.shared.b16 {%0,%1,%2,%3}, [%4];\n"
                 : "=r"(a0), "=r"(a1), "=r"(a2), "=r"(a3) : "r"(s));
}
__device__ __forceinline__ void ldsm2(uint32_t& a0, uint32_t& a1, const uint32_t* p) {
    uint32_t s = (uint32_t)__cvta_generic_to_shared(p);
    asm volatile("ldmatrix.sync.aligned.m8n8.x2.shared.b16 {%0,%1}, [%2];\n"
                 : "=r"(a0), "=r"(a1) : "r"(s));
}
__device__ __forceinline__ void ldsm2t(uint32_t& a0, uint32_t& a1, const uint32_t* p) {
    uint32_t s = (uint32_t)__cvta_generic_to_shared(p);
    asm volatile("ldmatrix.sync.aligned.m8n8.x2.trans.shared.b16 {%0,%1}, [%2];\n"
                 : "=r"(a0), "=r"(a1) : "r"(s));
}
__device__ __forceinline__ void mma16(float c[4], const uint32_t a[4], const uint32_t b[2]) {
    asm volatile(
        "mma.sync.aligned.m16n8k16.row.col.f32.bf16.bf16.f32 "
        "{%0,%1,%2,%3}, {%4,%5,%6,%7}, {%8,%9}, {%0,%1,%2,%3};\n"
        : "+f"(c[0]), "+f"(c[1]), "+f"(c[2]), "+f"(c[3])
        : "r"(a[0]), "r"(a[1]), "r"(a[2]), "r"(a[3]), "r"(b[0]), "r"(b[1]));
}
__device__ __forceinline__ void split2(float a, float b, uint32_t& hi, uint32_t& lo) {
    __nv_bfloat162 h = __floats2bfloat162_rn(a, b);
    hi = *reinterpret_cast<uint32_t*>(&h);
    float la = a - __bfloat162float(h.x);
    float lb = b - __bfloat162float(h.y);
    __nv_bfloat162 l = __floats2bfloat162_rn(la, lb);
    lo = *reinterpret_cast<uint32_t*>(&l);
}

// ---------------- batched abs-sum / quant / split (float4) ------------------
__global__ void abs_sum4(const float* __restrict__ w0, const float* __restrict__ w1,
                         const float* __restrict__ w2, const float* __restrict__ w3,
                         int n0, int n1, int n2, int n3, float* out) {
    int z = blockIdx.y;
    const float* w = z==0?w0 : z==1?w1 : z==2?w2 : w3;
    int n4 = (z==0?n0 : z==1?n1 : z==2?n2 : n3) >> 2;
    float s = 0.f;
    for (int i = blockIdx.x*blockDim.x + threadIdx.x; i < n4; i += gridDim.x*blockDim.x) {
        float4 v = ((const float4*)w)[i];
        s += fabsf(v.x) + fabsf(v.y) + fabsf(v.z) + fabsf(v.w);
    }
    #pragma unroll
    for (int o = 16; o; o >>= 1) s += __shfl_down_sync(0xffffffffu, s, o);
    __shared__ float sh[8];
    if ((threadIdx.x & 31) == 0) sh[threadIdx.x >> 5] = s;
    __syncthreads();
    if (threadIdx.x < 8) {
        float v = sh[threadIdx.x];
        #pragma unroll
        for (int o = 4; o; o >>= 1) v += __shfl_down_sync(0xffu, v, o);
        if (threadIdx.x == 0) atomicAdd(out + z, v);
    }
}

__global__ void quant4(const float* __restrict__ w0, const float* __restrict__ w1,
                       const float* __restrict__ w2, const float* __restrict__ w3,
                       __nv_bfloat16* __restrict__ q0, __nv_bfloat16* __restrict__ q1,
                       __nv_bfloat16* __restrict__ q2, __nv_bfloat16* __restrict__ q3,
                       const float* __restrict__ sums, int n0, int n1, int n2, int n3) {
    int z = blockIdx.y;
    const float* w = z==0?w0 : z==1?w1 : z==2?w2 : w3;
    __nv_bfloat16* q = z==0?q0 : z==1?q1 : z==2?q2 : q3;
    int n = z==0?n0 : z==1?n1 : z==2?n2 : n3;
    float s = sums[z] / (float)n + 1e-8f;
    float inv = 1.0f / s;
    int n4 = n >> 2;
    for (int i = blockIdx.x*blockDim.x + threadIdx.x; i < n4; i += gridDim.x*blockDim.x) {
        float4 v = ((const float4*)w)[i];
        float t0 = fminf(1.f, fmaxf(-1.f, rintf(v.x * inv)));   // half-to-even
        float t1 = fminf(1.f, fmaxf(-1.f, rintf(v.y * inv)));
        float t2 = fminf(1.f, fmaxf(-1.f, rintf(v.z * inv)));
        float t3 = fminf(1.f, fmaxf(-1.f, rintf(v.w * inv)));
        __nv_bfloat162 p0 = __floats2bfloat162_rn(t0, t1);
        __nv_bfloat162 p1 = __floats2bfloat162_rn(t2, t3);
        uint2 o = { *(uint32_t*)&p0, *(uint32_t*)&p1 };
        ((uint2*)q)[i] = o;
    }
}

__global__ void split4(const float* __restrict__ w0, const float* __restrict__ w1,
                       const float* __restrict__ w2, const float* __restrict__ w3,
                       __nv_bfloat16* __restrict__ h0, __nv_bfloat16* __restrict__ h1,
                       __nv_bfloat16* __restrict__ h2, __nv_bfloat16* __restrict__ h3,
                       __nv_bfloat16* __restrict__ l0, __nv_bfloat16* __restrict__ l1,
                       __nv_bfloat16* __restrict__ l2, __nv_bfloat16* __restrict__ l3,
                       int n0, int n1, int n2, int n3) {
    int z = blockIdx.y;
    const float* w = z==0?w0 : z==1?w1 : z==2?w2 : w3;
    __nv_bfloat16* hh = z==0?h0 : z==1?h1 : z==2?h2 : h3;
    __nv_bfloat16* ll = z==0?l0 : z==1?l1 : z==2?l2 : l3;
    int n4 = (z==0?n0 : z==1?n1 : z==2?n2 : n3) >> 2;
    for (int i = blockIdx.x*blockDim.x + threadIdx.x; i < n4; i += gridDim.x*blockDim.x) {
        float4 v = ((const float4*)w)[i];
        uint32_t h01, l01, h23, l23;
        split2(v.x, v.y, h01, l01);
        split2(v.z, v.w, h23, l23);
        uint2 ho = {h01, h23}, lo = {l01, l23};
        ((uint2*)hh)[i] = ho;
        ((uint2*)ll)[i] = lo;
    }
}

// ---------------- block reduce ------------------------------------------------
__device__ __forceinline__ float blockReduceSum(float v) {
    __shared__ float sh[33];
    __syncthreads();
    int lane = threadIdx.x & 31, wid = threadIdx.x >> 5;
    #pragma unroll
    for (int o = 16; o; o >>= 1) v += __shfl_down_sync(0xffffffffu, v, o);
    if (!lane) sh[wid] = v;
    __syncthreads();
    if (threadIdx.x < 8) {
        float t = sh[threadIdx.x];
        #pragma unroll
        for (int o = 4; o; o >>= 1) t += __shfl_down_sync(0xffu, t, o);
        if (!threadIdx.x) sh[32] = t;
    }
    __syncthreads();
    return sh[32];
}

// ---------------- split-K reduction: C = (p0+p1)*s + bias + resid -----------
__global__ void __launch_bounds__(256) reduce_add(
    const float4* __restrict__ p0, const float4* __restrict__ p1,
    const float* __restrict__ sumptr, float wcount,
    const float4* __restrict__ bias, const float4* __restrict__ resid,
    float4* __restrict__ C, int n4, int N4)
{
    float s = 1.0f;
    if (sumptr) s = sumptr[0] / wcount + 1e-8f;
    int i = blockIdx.x * blockDim.x + threadIdx.x;
    if (i < n4) {
        float4 a = p0[i], b = p1[i];
        float4 bb = bias[i % N4];
        float4 r = resid[i];
        C[i] = make_float4((a.x + b.x) * s + bb.x + r.x,
                           (a.y + b.y) * s + bb.y + r.y,
                           (a.z + b.z) * s + bb.z + r.z,
                           (a.w + b.w) * s + bb.w + r.w);
    }
}

// ---------------- fused split-K reduce + residual + LN(split bf16) ----------
// One block per row (width DIMM). h updated in place; ah/al emitted for the
// NEXT layer's ln1. Summation order identical to ln_kernel.
__global__ void __launch_bounds__(256) reduce_ln(
    const float4* __restrict__ p0, const float4* __restrict__ p1,
    const float* __restrict__ sumptr, float wcount,
    const float4* __restrict__ bias, float4* __restrict__ hbuf,
    const float* __restrict__ g, const float* __restrict__ b,
    __nv_bfloat16* __restrict__ yh, __nv_bfloat16* __restrict__ yl)
{
    const int n4 = DIMM >> 2;               // 192
    int t = threadIdx.x;
    size_t base = (size_t)blockIdx.x * n4;
    float s = 1.0f;
    if (sumptr) s = sumptr[0] / wcount + 1e-8f;
    float4 v;
    float sum = 0.f;
    if (t < n4) {
        float4 a = p0[base + t], c = p1[base + t];
        float4 bb = bias[t];
        float4 r = hbuf[base + t];
        v = make_float4((a.x + c.x) * s + bb.x + r.x,
                        (a.y + c.y) * s + bb.y + r.y,
                        (a.z + c.z) * s + bb.z + r.z,
                        (a.w + c.w) * s + bb.w + r.w);
        hbuf[base + t] = v;
        sum = v.x + v.y + v.z + v.w;
    }
    float m = blockReduceSum(sum) / (float)DIMM;
    float v2 = 0.f;
    if (t < n4) {
        float dx = v.x - m, dy = v.y - m, dz = v.z - m, dw = v.w - m;
        v2 = dx*dx + dy*dy + dz*dz + dw*dw;
    }
    float var = blockReduceSum(v2) / (float)DIMM;
    float r = rsqrtf(var + 1e-5f);
    if (t < n4) {
        float4 gg = ((const float4*)g)[t];
        float4 bb2 = ((const float4*)b)[t];
        float o0 = (v.x - m) * r * gg.x + bb2.x;
        float o1 = (v.y - m) * r * gg.y + bb2.y;
        float o2 = (v.z - m) * r * gg.z + bb2.z;
        float o3 = (v.w - m) * r * gg.w + bb2.w;
        uint32_t h01, l01, h23, l23;
        split2(o0, o1, h01, l01);
        split2(o2, o3, h23, l23);
        uint2 ho = {h01, h23}, lo = {l01, l23};
        ((uint2*)yh)[base + t] = ho;
        ((uint2*)yl)[base + t] = lo;
    }
}

// ---------------- layernorm -> split bf16 (register-resident) ----------------
__global__ void __launch_bounds__(256) ln_kernel(const float* __restrict__ x,
                                                 __nv_bfloat16* __restrict__ yh,
                                                 __nv_bfloat16* __restrict__ yl,
                                                 const float* __restrict__ g,
                                                 const float* __restrict__ b,
                                                 int width) {
    int t = threadIdx.x;
    int n4 = width >> 2;
    const float4* xr = (const float4*)(x + (size_t)blockIdx.x * width);
    float4 v[3];
    float s = 0.f;
    #pragma unroll
    for (int c = 0; c < 3; c++) {
        int i = t + c*256;
        if (i < n4) {
            v[c] = xr[i];
            s += v[c].x + v[c].y + v[c].z + v[c].w;
        }
    }
    float m = blockReduceSum(s) / (float)width;
    float v2 = 0.f;
    #pragma unroll
    for (int c = 0; c < 3; c++) {
        int i = t + c*256;
        if (i < n4) {
            float dx = v[c].x - m, dy = v[c].y - m, dz = v[c].z - m, dw = v[c].w - m;
            v2 += dx*dx + dy*dy + dz*dz + dw*dw;
        }
    }
    float var = blockReduceSum(v2) / (float)width;
    float r = rsqrtf(var + 1e-5f);
    uint2* yhr = (uint2*)(yh + (size_t)blockIdx.x * width);
    uint2* ylr = (uint2*)(yl + (size_t)blockIdx.x * width);
    #pragma unroll
    for (int c = 0; c < 3; c++) {
        int i = t + c*256;
        if (i < n4) {
            float4 gg = ((const float4*)g)[i];
            float4 bb = ((const float4*)b)[i];
            float o0 = (v[c].x - m) * r * gg.x + bb.x;
            float o1 = (v[c].y - m) * r * gg.y + bb.y;
            float o2 = (v[c].z - m) * r * gg.z + bb.z;
            float o3 = (v[c].w - m) * r * gg.w + bb.w;
            uint32_t h01, l01, h23, l23;
            split2(o0, o1, h01, l01);
            split2(o2, o3, h23, l23);
            uint2 ho = {h01, h23}, lo = {l01, l23};
            yhr[i] = ho;
            ylr[i] = lo;
        }
    }
}

// ---------------- bf16 tensor-core GEMM (2-stage, 1 sync/step) ---------------
// C = s*(A @ W^T) + bias [+gelu] [+resid]
// EPI: 0 fp32 out, 1 fp32+GELU, 2 split-bf16 out (QKV), 3 raw partial (split-K)
// SPLIT: K-range split across blockIdx.z (partials reduced by reduce_add/_ln)
template<int CHAINS> struct GCfg {
    static const int BK  = (CHAINS == 2) ? 64 : 32;
    static const int WPR = BK / 2;          // words per row chunk
    static const int GW  = WPR + 4;         // padded row stride (words)
    static const int GT  = 128 * GW;        // words per array per stage
    static const int SM  = 2 * (CHAINS + 1) * GT * 4;   // smem bytes
};
#define GSMEM2 (GCfg<2>::SM)   /* 110592 */
#define GSMEM3 (GCfg<3>::SM)   /* 81920  */

template<int CHAINS, int EPI, int SPLIT>
__global__ void __launch_bounds__(256,2) gemm_bf16(
    const uint32_t* __restrict__ AHg, const uint32_t* __restrict__ ALg,
    const uint32_t* __restrict__ WHg, const uint32_t* __restrict__ WLg,
    const float* __restrict__ sumptr, float wcount,
    const float* __restrict__ bias, const float* __restrict__ resid,
    float* __restrict__ C, int M, int N, int K)
{
    extern __shared__ uint32_t smw[];
    const int BK  = GCfg<CHAINS>::BK;
    const int WPR = GCfg<CHAINS>::WPR;
    const int GW  = GCfg<CHAINS>::GW;
    const int GT  = GCfg<CHAINS>::GT;
    const int PS  = (CHAINS + 1) * GT;
    const int NG  = BK / 16;                // k16 groups per step
    const int TPR = WPR / 4;                // copy threads per row
    const int RPP = 256 / TPR;              // rows per copy pass
    int t = threadIdx.x, lane = t & 31, wid = t >> 5;
    int wm = wid & 3, wn = wid >> 2;        // 4x2 warp grid: 32m x 64n per warp
    int bm = blockIdx.y * 128, bn = blockIdx.x * 128;
    int Kw = K >> 1;
    int kwb = (SPLIT == 2) ? (int)blockIdx.z * (Kw >> 1) : 0;
    float* Cp = (EPI == 3) ? (C + (size_t)blockIdx.z * PPLANE) : C;
    float acc[2][8][4] = {};

    int crow = t / TPR, cwg = (t % TPR) << 2;

    auto do_copy = [&](int slot, int kw) {
        uint32_t* S = smw + slot*PS;
        #pragma unroll
        for (int it = 0; it < 128/RPP; it++) {
            int row = it*RPP + crow;
            cp_async16(S +        row*GW + cwg, AHg + (size_t)(bm+row)*Kw + kw + cwg);
            cp_async16(S +   GT + row*GW + cwg, ALg + (size_t)(bm+row)*Kw + kw + cwg);
            cp_async16(S + 2*GT + row*GW + cwg, WHg + (size_t)(bn+row)*Kw + kw + cwg);
            if (CHAINS == 3)
                cp_async16(S + 3*GT + row*GW + cwg, WLg + (size_t)(bn+row)*Kw + kw + cwg);
        }
        asm volatile("cp.async.commit_group;\n");
    };

    int nsteps = K / (BK * SPLIT);
    do_copy(0, kwb);

    int lsub = lane >> 3, lrow = lane & 7;
    int lmrow = (lsub & 1) * 8 + lrow;
    int lkoff = (lsub >> 1) * 4;
    int bl8 = lane & 7;
    int btile = lsub >> 1;
    int bkh = (lsub & 1) * 4;

    for (int i = 0; i < nsteps; i++) {
        asm volatile("cp.async.wait_group 0;\n");
        __syncthreads();
        if (i + 1 < nsteps) do_copy((i + 1) & 1, kwb + (i + 1) * WPR);

        uint32_t* S = smw + (i & 1) * PS;
        const uint32_t* AHs = S;
        const uint32_t* ALs = S + GT;
        const uint32_t* WHs = S + 2*GT;
        const uint32_t* WLs = S + 3*GT;

        #pragma unroll
        for (int g = 0; g < NG; g++) {
            uint32_t bh[8][2], bl[8][2];
            #pragma unroll
            for (int p = 0; p < 4; p++) {
                int brow = wn*64 + p*16 + btile*8 + bl8;
                ldsm4(bh[2*p][0], bh[2*p][1], bh[2*p+1][0], bh[2*p+1][1],
                      WHs + brow*GW + g*8 + bkh);
                if (CHAINS == 3)
                    ldsm4(bl[2*p][0], bl[2*p][1], bl[2*p+1][0], bl[2*p+1][1],
                          WLs + brow*GW + g*8 + bkh);
            }
            uint32_t ah[2][4], al[2][4];
            #pragma unroll
            for (int ii = 0; ii < 2; ii++) {
                int mr = wm*32 + ii*16 + lmrow;
                int kc = g*8 + lkoff;
                ldsm4(ah[ii][0], ah[ii][1], ah[ii][2], ah[ii][3], AHs + mr*GW + kc);
                ldsm4(al[ii][0], al[ii][1], al[ii][2], al[ii][3], ALs + mr*GW + kc);
            }
            // hi chain first (16 independent accumulators), then lo chain
            #pragma unroll
            for (int ii = 0; ii < 2; ii++)
                #pragma unroll
                for (int j = 0; j < 8; j++)
                    mma16(acc[ii][j], ah[ii], bh[j]);
            #pragma unroll
            for (int ii = 0; ii < 2; ii++)
                #pragma unroll
                for (int j = 0; j < 8; j++)
                    mma16(acc[ii][j], al[ii], bh[j]);
            if (CHAINS == 3) {
                #pragma unroll
                for (int ii = 0; ii < 2; ii++)
                    #pragma unroll
                    for (int j = 0; j < 8; j++)
                        mma16(acc[ii][j], ah[ii], bl[j]);
            }
        }
    }

    float s = 1.0f;
    if (EPI != 3 && sumptr) s = sumptr[0] / wcount + 1e-8f;
    #pragma unroll
    for (int i = 0; i < 2; i++) {
        int r0 = bm + wm*32 + i*16 + (lane >> 2);
        #pragma unroll
        for (int j = 0; j < 8; j++) {
            int c0 = bn + wn*64 + j*8 + ((lane & 3) << 1);
            float v[4] = {acc[i][j][0]*s, acc[i][j][1]*s, acc[i][j][2]*s, acc[i][j][3]*s};
            if (EPI == 3) {
                *(float2*)(Cp + (size_t)r0*N + c0)     = make_float2(v[0], v[1]);
                *(float2*)(Cp + (size_t)(r0+8)*N + c0) = make_float2(v[2], v[3]);
                continue;
            }
            if (bias) { v[0] += bias[c0]; v[1] += bias[c0+1]; v[2] += bias[c0]; v[3] += bias[c0+1]; }
            if (EPI == 1) {
                #pragma unroll
                for (int u = 0; u < 4; u++)
                    v[u] = v[u] * 0.5f * (1.0f + erff(v[u] * 0.70710678118654752f));
            }
            if (resid) {
                float2 r1 = *(const float2*)(resid + (size_t)r0*N + c0);
                float2 r2 = *(const float2*)(resid + (size_t)(r0+8)*N + c0);
                v[0] += r1.x; v[1] += r1.y; v[2] += r2.x; v[3] += r2.y;
            }
            if (EPI == 2) {
                float mult = (c0 < INNER) ? SCALE : 1.0f;
                uint32_t* Ch = (uint32_t*)C;
                uint32_t* Cl = Ch + QPLANE;
                uint32_t h01, l01, h23, l23;
                split2(v[0]*mult, v[1]*mult, h01, l01);
                split2(v[2]*mult, v[3]*mult, h23, l23);
                int cw = c0 >> 1, Nw = N >> 1;
                Ch[(size_t)r0*Nw + cw]     = h01; Cl[(size_t)r0*Nw + cw]     = l01;
                Ch[(size_t)(r0+8)*Nw + cw] = h23; Cl[(size_t)(r0+8)*Nw + cw] = l23;
            } else {
                *(float2*)(C + (size_t)r0*N + c0)     = make_float2(v[0], v[1]);
                *(float2*)(C + (size_t)(r0+8)*N + c0) = make_float2(v[2], v[3]);
            }
        }
    }
}

// ---------------- tensor-core flash attention (pre-split bf16 input) ---------
#define AW 36    /* words per 64-dhead row (32 + 4 pad; 144B, 16B-aligned) */
#define AQW (128*AW)
#define AKW (64*AW)
#define AFSMEM ((2*AQW + 4*AKW)*4)   /* 73728 B */

__global__ void __launch_bounds__(256,2) attn_flash(const uint32_t* __restrict__ qh,
                                                    const uint32_t* __restrict__ ql,
                                                    float* __restrict__ O) {
    extern __shared__ uint32_t asw[];
    uint32_t* Qh = asw;
    uint32_t* Ql = asw + AQW;
    uint32_t* Kh = asw + 2*AQW;
    uint32_t* Kl = Kh + AKW;
    uint32_t* Vh = Kl + AKW;
    uint32_t* Vl = Vh + AKW;

    int t = threadIdx.x, lane = t & 31, wid = t >> 5;
    int bh = blockIdx.y;
    int b = bh / HEADS, hh = bh % HEADS;
    int m0 = blockIdx.x * 128;
    int hw = hh * (DHEAD/2);             // 32-word head offset

    #pragma unroll
    for (int it = 0; it < 4; it++) {
        int idx = it*256 + t;
        int row = idx >> 3, wg = (idx & 7) << 2;
        size_t src = (size_t)(b*SEQ + m0 + row) * QKVW + hw + wg;
        *(uint4*)(Qh + row*AW + wg) = *(const uint4*)(qh + src);
        *(uint4*)(Ql + row*AW + wg) = *(const uint4*)(ql + src);
    }
    __syncthreads();

    int lsub = lane >> 3, lrow = lane & 7;
    int mr = wid*16 + (lsub & 1)*8 + lrow;
    int lk = (lsub >> 1) * 4;
    uint32_t qfh[4][4], qfl[4][4];
    #pragma unroll
    for (int g = 0; g < 4; g++) {
        ldsm4(qfh[g][0], qfh[g][1], qfh[g][2], qfh[g][3], Qh + mr*AW + g*8 + lk);
        ldsm4(qfl[g][0], qfl[g][1], qfl[g][2], qfl[g][3], Ql + mr*AW + g*8 + lk);
    }

    float mi0 = -1e30f, mi1 = -1e30f, li0 = 0.f, li1 = 0.f;
    float acc[8][4] = {};

    for (int kv = 0; kv < SEQ; kv += 64) {
        __syncthreads();
        #pragma unroll
        for (int it = 0; it < 2; it++) {
            int idx = it*256 + t;
            int row = idx >> 3, wg = (idx & 7) << 2;
            size_t rb = (size_t)(b*SEQ + kv + row) * QKVW;
            int w = row*AW + wg;
            *(uint4*)(Kh + w) = *(const uint4*)(qh + rb + (INNER/2)   + hw + wg);
            *(uint4*)(Kl + w) = *(const uint4*)(ql + rb + (INNER/2)   + hw + wg);
            *(uint4*)(Vh + w) = *(const uint4*)(qh + rb + INNER       + hw + wg);
            *(uint4*)(Vl + w) = *(const uint4*)(ql + rb + INNER       + hw + wg);
        }
        __syncthreads();

        float s[8][4] = {};
        int koff = ((lane >> 3) & 1) * 4;
        #pragma unroll
        for (int g = 0; g < 4; g++) {
            #pragma unroll
            for (int j = 0; j < 8; j++) {
                const uint32_t* pk = Kh + (j*8 + (lane & 7))*AW + g*8 + koff;
                uint32_t bhv[2], blv[2];
                ldsm2(bhv[0], bhv[1], pk);
                ldsm2(blv[0], blv[1], Kl + (j*8 + (lane & 7))*AW + g*8 + koff);
                mma16(s[j], qfh[g], bhv);
                mma16(s[j], qfl[g], bhv);
                mma16(s[j], qfh[g], blv);
            }
        }

        float rm0 = -1e30f, rm1 = -1e30f;
        #pragma unroll
        for (int j = 0; j < 8; j++) {
            rm0 = fmaxf(rm0, fmaxf(s[j][0], s[j][1]));
            rm1 = fmaxf(rm1, fmaxf(s[j][2], s[j][3]));
        }
        rm0 = fmaxf(rm0, __shfl_xor_sync(0xffffffffu, rm0, 1));
        rm0 = fmaxf(rm0, __shfl_xor_sync(0xffffffffu, rm0, 2));
        rm1 = fmaxf(rm1, __shfl_xor_sync(0xffffffffu, rm1, 1));
        rm1 = fmaxf(rm1, __shfl_xor_sync(0xffffffffu, rm1, 2));
        float mn0 = fmaxf(mi0, rm0), mn1 = fmaxf(mi1, rm1);
        float f0 = __expf(mi0 - mn0), f1 = __expf(mi1 - mn1);
        mi0 = mn0; mi1 = mn1;
        float sum0 = 0.f, sum1 = 0.f;
        #pragma unroll
        for (int j = 0; j < 8; j++) {
            s[j][0] = __expf(s[j][0] - mn0); s[j][1] = __expf(s[j][1] - mn0);
            s[j][2] = __expf(s[j][2] - mn1); s[j][3] = __expf(s[j][3] - mn1);
            sum0 += s[j][0] + s[j][1];
            sum1 += s[j][2] + s[j][3];
        }
        sum0 += __shfl_xor_sync(0xffffffffu, sum0, 1);
        sum0 += __shfl_xor_sync(0xffffffffu, sum0, 2);
        sum1 += __shfl_xor_sync(0xffffffffu, sum1, 1);
        sum1 += __shfl_xor_sync(0xffffffffu, sum1, 2);
        li0 = li0*f0 + sum0; li1 = li1*f1 + sum1;
        #pragma unroll
        for (int j = 0; j < 8; j++) {
            acc[j][0] *= f0; acc[j][1] *= f0;
            acc[j][2] *= f1; acc[j][3] *= f1;
        }

        #pragma unroll
        for (int g = 0; g < 4; g++) {
            uint32_t aph[4], apl[4];
            split2(s[2*g][0],   s[2*g][1],   aph[0], apl[0]);
            split2(s[2*g][2],   s[2*g][3],   aph[1], apl[1]);
            split2(s[2*g+1][0], s[2*g+1][1], aph[2], apl[2]);
            split2(s[2*g+1][2], s[2*g+1][3], aph[3], apl[3]);
            #pragma unroll
            for (int j = 0; j < 8; j++) {
                const uint32_t* pv = Vh + (g*16 + (lane & 15))*AW + j*4;
                uint32_t bhv[2], blv[2];
                ldsm2t(bhv[0], bhv[1], pv);
                ldsm2t(blv[0], blv[1], Vl + (g*16 + (lane & 15))*AW + j*4);
                mma16(acc[j], aph, bhv);
                mma16(acc[j], apl, bhv);
                mma16(acc[j], aph, blv);
            }
        }
    }

    float inv0 = 1.0f / li0, inv1 = 1.0f / li1;
    int r = m0 + wid*16 + (lane >> 2);
    #pragma unroll
    for (int j = 0; j < 8; j++) {
        int col = hh*DHEAD + j*8 + ((lane & 3) << 1);
        float2 o0 = {acc[j][0]*inv0, acc[j][1]*inv0};
        float2 o1 = {acc[j][2]*inv1, acc[j][3]*inv1};
        *(float2*)(O + ((size_t)b*SEQ + r)*INNER + col)     = o0;
        *(float2*)(O + ((size_t)b*SEQ + r + 8)*INNER + col) = o1;
    }
}

// ---------------- host driver -----------------------------------------------
extern "C" void kernel_launch(void* const* d_in, const int* in_sizes, int n_in,
                              void* d_out, int out_size) {
    const float* x    = (const float*)d_in[0];
    const float* ln1g = (const float*)d_in[1];
    const float* ln1b = (const float*)d_in[2];
    const float* Wqkv = (const float*)d_in[3];
    const float* ln2g = (const float*)d_in[4];
    const float* ln2b = (const float*)d_in[5];
    const float* Wo   = (const float*)d_in[6];
    const float* bo   = (const float*)d_in[7];
    const float* f1g  = (const float*)d_in[8];
    const float* f1b  = (const float*)d_in[9];
    const float* W1   = (const float*)d_in[10];
    const float* b1   = (const float*)d_in[11];
    const float* f2g  = (const float*)d_in[12];
    const float* f2b  = (const float*)d_in[13];
    const float* W2   = (const float*)d_in[14];
    const float* b2   = (const float*)d_in[15];
    float* h = (float*)d_out;

    float *qkv, *ob, *mlp, *part, *scal;
    __nv_bfloat16 *ah, *al, *whq, *wlq, *who, *wlo, *wh1, *wl1, *wh2, *wl2;
    cudaGetSymbolAddress((void**)&qkv, g_qkv);
    cudaGetSymbolAddress((void**)&ob,  g_obuf);
    cudaGetSymbolAddress((void**)&mlp, g_mlp);
    cudaGetSymbolAddress((void**)&part, g_part);
    cudaGetSymbolAddress((void**)&ah,  g_ah);
    cudaGetSymbolAddress((void**)&al,  g_al);
    cudaGetSymbolAddress((void**)&whq, g_whq);
    cudaGetSymbolAddress((void**)&wlq, g_wlq);
    cudaGetSymbolAddress((void**)&who, g_who);
    cudaGetSymbolAddress((void**)&wlo, g_wlo);
    cudaGetSymbolAddress((void**)&wh1, g_wh1);
    cudaGetSymbolAddress((void**)&wl1, g_wl1);
    cudaGetSymbolAddress((void**)&wh2, g_wh2);
    cudaGetSymbolAddress((void**)&wl2, g_wl2);
    cudaGetSymbolAddress((void**)&scal, g_scal);

    cudaFuncSetAttribute(gemm_bf16<2,0,1>, cudaFuncAttributeMaxDynamicSharedMemorySize, GSMEM2);
    cudaFuncSetAttribute(gemm_bf16<2,1,1>, cudaFuncAttributeMaxDynamicSharedMemorySize, GSMEM2);
    cudaFuncSetAttribute(gemm_bf16<2,2,1>, cudaFuncAttributeMaxDynamicSharedMemorySize, GSMEM2);
    cudaFuncSetAttribute(gemm_bf16<2,3,2>, cudaFuncAttributeMaxDynamicSharedMemorySize, GSMEM2);
    cudaFuncSetAttribute(gemm_bf16<3,0,1>, cudaFuncAttributeMaxDynamicSharedMemorySize, GSMEM3);
    cudaFuncSetAttribute(gemm_bf16<3,1,1>, cudaFuncAttributeMaxDynamicSharedMemorySize, GSMEM3);
    cudaFuncSetAttribute(gemm_bf16<3,2,1>, cudaFuncAttributeMaxDynamicSharedMemorySize, GSMEM3);
    cudaFuncSetAttribute(gemm_bf16<3,3,2>, cudaFuncAttributeMaxDynamicSharedMemorySize, GSMEM3);
    cudaFuncSetAttribute(attn_flash,       cudaFuncAttributeMaxDynamicSharedMemorySize, AFSMEM);

    cudaMemcpyAsync(h, x, sizeof(float)*(size_t)ROWS*DIMM, cudaMemcpyDeviceToDevice);

    const int nA = NQKV*DIMM, nO = DIMM*INNER, n1 = MLPD*DIMM, n2 = DIMM*MLPD;
    const int RN4 = ROWS*DIMM/4;   // float4 count for reduce
    const int N4  = DIMM/4;

    for (int l = 0; l < DEPTH; l++) {
        bool tern = (l < DEPTH - 1);
        if (tern) {
            cudaMemsetAsync(scal, 0, 4*sizeof(float));
            abs_sum4<<<dim3(160,4),256>>>(
                Wqkv + (size_t)l*nA, Wo + (size_t)l*nO, W1 + (size_t)l*n1, W2 + (size_t)l*n2,
                nA, nO, n1, n2, scal);
            quant4<<<dim3(160,4),256>>>(
                Wqkv + (size_t)l*nA, Wo + (size_t)l*nO, W1 + (size_t)l*n1, W2 + (size_t)l*n2,
                whq, who, wh1, wh2, scal, nA, nO, n1, n2);
        } else {
            split4<<<dim3(160,4),256>>>(
                Wqkv + (size_t)l*nA, Wo + (size_t)l*nO, W1 + (size_t)l*n1, W2 + (size_t)l*n2,
                whq, who, wh1, wh2, wlq, wlo, wl1, wl2, nA, nO, n1, n2);
        }

        // attention block (QKV gemm emits pre-split, Q pre-scaled bf16)
        if (l == 0)   // later layers: ah/al produced by previous reduce_ln
            ln_kernel<<<ROWS,256>>>(h, ah, al, ln1g + l*DIMM, ln1b + l*DIMM, DIMM);
        if (tern)
            gemm_bf16<2,2,1><<<dim3(NQKV/128, ROWS/128),256,GSMEM2>>>(
                (uint32_t*)ah, (uint32_t*)al, (uint32_t*)whq, nullptr,
                scal+0, (float)nA, nullptr, nullptr, qkv, ROWS, NQKV, DIMM);
        else
            gemm_bf16<3,2,1><<<dim3(NQKV/128, ROWS/128),256,GSMEM3>>>(
                (uint32_t*)ah, (uint32_t*)al, (uint32_t*)whq, (uint32_t*)wlq,
                nullptr, 1.0f, nullptr, nullptr, qkv, ROWS, NQKV, DIMM);
        attn_flash<<<dim3(SEQ/128, BB*HEADS),256,AFSMEM>>>(
            (uint32_t*)qkv, (uint32_t*)qkv + QPLANE, ob);
        ln_kernel<<<ROWS,256>>>(ob, ah, al, ln2g + l*INNER, ln2b + l*INNER, INNER);
        if (tern)
            gemm_bf16<2,0,1><<<dim3(DIMM/128, ROWS/128),256,GSMEM2>>>(
                (uint32_t*)ah, (uint32_t*)al, (uint32_t*)who, nullptr,
                scal+1, (float)nO, bo + l*DIMM, h, h, ROWS, DIMM, INNER);
        else
            gemm_bf16<3,0,1><<<dim3(DIMM/128, ROWS/128),256,GSMEM3>>>(
                (uint32_t*)ah, (uint32_t*)al, (uint32_t*)who, (uint32_t*)wlo,
                nullptr, 1.0f, bo + l*DIMM, h, h, ROWS, DIMM, INNER);

        // MLP block (GELU fused into FF1 epilogue; FF2 split-K=2)
        ln_kernel<<<ROWS,256>>>(h, ah, al, f1g + l*DIMM, f1b + l*DIMM, DIMM);
        if (tern)
            gemm_bf16<2,1,1><<<dim3(MLPD/128, ROWS/128),256,GSMEM2>>>(
                (uint32_t*)ah, (uint32_t*)al, (uint32_t*)wh1, nullptr,
                scal+2, (float)n1, b1 + l*MLPD, nullptr, mlp, ROWS, MLPD, DIMM);
        else
            gemm_bf16<3,1,1><<<dim3(MLPD/128, ROWS/128),256,GSMEM3>>>(
                (uint32_t*)ah, (uint32_t*)al, (uint32_t*)wh1, (uint32_t*)wl1,
                nullptr, 1.0f, b1 + l*MLPD, nullptr, mlp, ROWS, MLPD, DIMM);
        ln_kernel<<<ROWS,256>>>(mlp, ah, al, f2g + l*MLPD, f2b + l*MLPD, MLPD);
        if (tern) {
            gemm_bf16<2,3,2><<<dim3(DIMM/128, ROWS/128, 2),256,GSMEM2>>>(
                (uint32_t*)ah, (uint32_t*)al, (uint32_t*)wh2, nullptr,
                nullptr, 1.0f, nullptr, nullptr, part, ROWS, DIMM, MLPD);
            // fused: h update + ln1 of layer l+1 (l<5 always true here)
            reduce_ln<<<ROWS,256>>>(
                (const float4*)part, (const float4*)(part + PPLANE),
                scal+3, (float)n2, (const float4*)(b2 + l*DIMM), (float4*)h,
                ln1g + (l+1)*DIMM, ln1b + (l+1)*DIMM, ah, al);
        } else {
            gemm_bf16<3,3,2><<<dim3(DIMM/128, ROWS/128, 2),256,GSMEM3>>>(
                (uint32_t*)ah, (uint32_t*)al, (uint32_t*)wh2, (uint32_t*)wl2,
                nullptr, 1.0f, nullptr, nullptr, part, ROWS, DIMM, MLPD);
            reduce_add<<<(RN4+255)/256,256>>>(
                (const float4*)part, (const float4*)(part + PPLANE),
                nullptr, 1.0f, (const float4*)(b2 + l*DIMM),
                (const float4*)h, (float4*)h, RN4, N4);
        }
    }
}